// round 8
// baseline (speedup 1.0000x reference)
#include <cuda_runtime.h>
#include <cuda_bf16.h>
#include <math.h>
#include <stdint.h>

#define LL 2
#define NN1 8
#define NN2 8
#define PP 1024
#define DD 768
#define PH 32
#define PW 32
#define IMG 512

// Scratch (device globals; no allocation allowed)
__device__ __nv_bfloat16 g_fa[LL * NN1 * PP * DD];  // normalized feats (bf16)
__device__ __nv_bfloat16 g_fb[LL * NN2 * PP * DD];  // normalized nfeats (bf16)
__device__ float g_maxdot[LL * NN1 * NN2 * PP];     // max_p2 cos-sim
__device__ float g_sp[LL * NN1 * NN2 * PP];
__device__ float g_maxp[LL * NN1 * NN2];
__device__ float g_spbar[NN1 * PP];

// ---------------------------------------------------------------------------
// Kernel 1: L2-normalize rows of [rows, 768] -> bf16. One warp per row.
// grid.y = 0 -> feats->g_fa, 1 -> nfeats->g_fb
// ---------------------------------------------------------------------------
__global__ __launch_bounds__(256) void normalize_kernel(const float* __restrict__ inA,
                                                        const float* __restrict__ inB,
                                                        int nrows) {
    int row  = blockIdx.x * 8 + (threadIdx.x >> 5);
    int lane = threadIdx.x & 31;
    if (row >= nrows) return;
    const float* in = blockIdx.y ? inB : inA;
    __nv_bfloat16* outbase = blockIdx.y ? g_fb : g_fa;
    const float4* src = (const float4*)(in + (size_t)row * DD);
    __nv_bfloat162* dst = (__nv_bfloat162*)(outbase + (size_t)row * DD);

    float4 v[6];
    float ss = 0.f;
#pragma unroll
    for (int i = 0; i < 6; i++) {
        v[i] = src[lane + 32 * i];
        ss += v[i].x * v[i].x + v[i].y * v[i].y + v[i].z * v[i].z + v[i].w * v[i].w;
    }
#pragma unroll
    for (int o = 16; o > 0; o >>= 1) ss += __shfl_xor_sync(0xffffffffu, ss, o);
    float inv = 1.0f / sqrtf(ss);
#pragma unroll
    for (int i = 0; i < 6; i++) {
        int e = lane + 32 * i;
        dst[e * 2 + 0] = __floats2bfloat162_rn(v[i].x * inv, v[i].y * inv);
        dst[e * 2 + 1] = __floats2bfloat162_rn(v[i].z * inv, v[i].w * inv);
    }
}

// ---------------------------------------------------------------------------
// Kernel 2: fused bf16 mma.sync GEMM + row-max (v3).
// Pair = (l,n1,n2): S = A[1024,768]*B[1024,768]^T; keep row max over columns.
// Block: 128-row strip of A. Flat 96-stage pipeline over (8 col tiles x 12
// K-stages of 64). 256 thr = 8 warps (2m x 4n), warp tile 64x32,
// mma.m16n8k16.bf16. 3-slot cp.async ring, prefetch depth 2, ONE
// __syncthreads per stage. 2 CTAs/SM.
// ---------------------------------------------------------------------------
#define BM 128
#define BN 128
#define RSB 144                 // smem row stride in bytes (128 + 16 pad)
#define ABUF (128 * RSB)        // one matrix buffer = 18432 B
#define SLOT (2 * ABUF)         // A+B per ring slot = 36864 B
#define OFF_PART (3 * SLOT)     // 110592
#define SMEM_BYTES (OFF_PART + 4 * 128 * 4)  // 112640

#define CP16(dst_u32, src_ptr) \
    asm volatile("cp.async.cg.shared.global [%0], [%1], 16;\n" :: "r"(dst_u32), "l"(src_ptr))

__device__ __forceinline__ void ldsm4(uint32_t* r, uint32_t addr) {
    asm volatile("ldmatrix.sync.aligned.m8n8.x4.shared.b16 {%0,%1,%2,%3}, [%4];"
                 : "=r"(r[0]), "=r"(r[1]), "=r"(r[2]), "=r"(r[3]) : "r"(addr));
}

__global__ __launch_bounds__(256, 2) void distmax_bf16_v3() {
    extern __shared__ char dsm[];
    uint32_t sm = (uint32_t)__cvta_generic_to_shared(dsm);
    float* part = (float*)(dsm + OFF_PART);

    const int pair = blockIdx.y;          // ((l*8 + n1)*8 + n2)
    const int l  = pair >> 6;
    const int n1 = (pair >> 3) & 7;
    const int n2 = pair & 7;
    const __nv_bfloat16* __restrict__ A =
        g_fa + (((size_t)(l * NN1 + n1)) * PP + blockIdx.x * BM) * DD;
    const __nv_bfloat16* __restrict__ B = g_fb + ((size_t)(l * NN2 + n2)) * PP * DD;

    const int tid  = threadIdx.x;
    const int lane = tid & 31;
    const int warp = tid >> 5;
    const int wm = warp >> 2;        // 0..1
    const int wn = warp & 3;         // 0..3
    const int g  = lane >> 2;        // 0..7
    const int t4 = lane & 3;         // 0..3
    const int sub = lane >> 3;       // 0..3 (ldmatrix sub-matrix)
    const int lr8 = lane & 7;

    // cp.async: 4 chunks per matrix per stage; each eighth-warp = one 128B row
    const int rB = tid >> 3;         // 0..31
    const int cc = tid & 7;          // 16B chunk within 128B row
    uint32_t dA[4], dB[4];
    const __nv_bfloat16 *aS[4], *bS[4];
#pragma unroll
    for (int i = 0; i < 4; i++) {
        int r = rB + 32 * i;
        dA[i] = sm + (uint32_t)(r * RSB + cc * 16);
        dB[i] = sm + ABUF + (uint32_t)(r * RSB + cc * 16);
        aS[i] = A + (size_t)r * DD + cc * 8;
        bS[i] = B + (size_t)r * DD + cc * 8;
    }

    // ldmatrix per-lane byte offsets within a slot (R4/R7-proven mapping):
    // A: rows from sub&1, k from sub>>1 ; B: rows from sub>>1, k from sub&1
    const uint32_t aLds = (uint32_t)((wm * 64 + (sub & 1) * 8 + lr8) * RSB +
                                     (sub >> 1) * 16);
    const uint32_t bLds = (uint32_t)(ABUF + (wn * 32 + (sub >> 1) * 8 + lr8) * RSB +
                                     (sub & 1) * 16);

    float rmax[4][2];
#pragma unroll
    for (int i = 0; i < 4; i++) { rmax[i][0] = -2.f; rmax[i][1] = -2.f; }

    // issue() loads the next sequential stage into the next ring slot.
    int ct_n = 0, k_n = 0;   // (ct,k) of NEXT stage to issue
    int ibuf = 0;            // ring slot of NEXT stage to issue
    auto issue = [&]() {
        uint32_t bo = (uint32_t)(ibuf * SLOT);
        int ko = k_n * 64;
        size_t bco = (size_t)ct_n * BN * DD + ko;
#pragma unroll
        for (int i = 0; i < 4; i++) CP16(dA[i] + bo, aS[i] + ko);
#pragma unroll
        for (int i = 0; i < 4; i++) CP16(dB[i] + bo, bS[i] + bco);
        asm volatile("cp.async.commit_group;\n");
        if (++k_n == 12) { k_n = 0; ct_n++; }
        if (++ibuf == 3) ibuf = 0;
    };

    issue();  // stage 0
    issue();  // stage 1

    float acc[4][4][4];
    int kc = 0;   // kstep within current column tile
    int cb = 0;   // ring slot of current compute stage

    for (int s = 0; s < 96; s++) {
        if (s + 1 < 96) {
            asm volatile("cp.async.wait_group 1;\n");
        } else {
            asm volatile("cp.async.wait_group 0;\n");
        }
        __syncthreads();
        if (s + 2 < 96) issue();

        if (kc == 0) {
#pragma unroll
            for (int mi = 0; mi < 4; mi++)
#pragma unroll
                for (int ni = 0; ni < 4; ni++)
#pragma unroll
                    for (int r = 0; r < 4; r++) acc[mi][ni][r] = 0.f;
        }

        const uint32_t base = sm + (uint32_t)(cb * SLOT);

#pragma unroll
        for (int k16 = 0; k16 < 4; k16++) {
            uint32_t a[4][4], b[2][4];
#pragma unroll
            for (int mi = 0; mi < 4; mi++)
                ldsm4(a[mi], base + aLds + (uint32_t)(mi * 16 * RSB + k16 * 32));
#pragma unroll
            for (int np = 0; np < 2; np++)
                ldsm4(b[np], base + bLds + (uint32_t)(np * 16 * RSB + k16 * 32));
#pragma unroll
            for (int mi = 0; mi < 4; mi++)
#pragma unroll
                for (int ni = 0; ni < 4; ni++) {
                    asm volatile(
                        "mma.sync.aligned.m16n8k16.row.col.f32.bf16.bf16.f32 "
                        "{%0,%1,%2,%3},{%4,%5,%6,%7},{%8,%9},{%0,%1,%2,%3};\n"
                        : "+f"(acc[mi][ni][0]), "+f"(acc[mi][ni][1]),
                          "+f"(acc[mi][ni][2]), "+f"(acc[mi][ni][3])
                        : "r"(a[mi][0]), "r"(a[mi][1]), "r"(a[mi][2]), "r"(a[mi][3]),
                          "r"(b[ni >> 1][(ni & 1) * 2]), "r"(b[ni >> 1][(ni & 1) * 2 + 1]));
                }
        }

        if (kc == 11) {
            // column tile finished: fold into running row max
            // c0,c1 -> row g; c2,c3 -> row g+8
#pragma unroll
            for (int mi = 0; mi < 4; mi++) {
                float m0 = -2.f, m1 = -2.f;
#pragma unroll
                for (int ni = 0; ni < 4; ni++) {
                    m0 = fmaxf(m0, fmaxf(acc[mi][ni][0], acc[mi][ni][1]));
                    m1 = fmaxf(m1, fmaxf(acc[mi][ni][2], acc[mi][ni][3]));
                }
                rmax[mi][0] = fmaxf(rmax[mi][0], m0);
                rmax[mi][1] = fmaxf(rmax[mi][1], m1);
            }
            kc = 0;
        } else {
            kc++;
        }
        if (++cb == 3) cb = 0;
    }

    // reduce across the 4 lanes sharing g (t4 = lane&3)
#pragma unroll
    for (int o = 1; o <= 2; o <<= 1) {
#pragma unroll
        for (int mi = 0; mi < 4; mi++) {
            rmax[mi][0] = fmaxf(rmax[mi][0], __shfl_xor_sync(0xffffffffu, rmax[mi][0], o));
            rmax[mi][1] = fmaxf(rmax[mi][1], __shfl_xor_sync(0xffffffffu, rmax[mi][1], o));
        }
    }
    if (t4 == 0) {
#pragma unroll
        for (int mi = 0; mi < 4; mi++) {
            int r = wm * 64 + mi * 16 + g;
            part[wn * 128 + r] = rmax[mi][0];
            part[wn * 128 + r + 8] = rmax[mi][1];
        }
    }
    __syncthreads();
    if (tid < 128) {
        float v = fmaxf(fmaxf(part[tid], part[128 + tid]),
                        fmaxf(part[256 + tid], part[384 + tid]));
        g_maxdot[(size_t)pair * PP + blockIdx.x * BM + tid] = v;
    }
}

// ---------------------------------------------------------------------------
// Kernel 3: sp = sqrt(max(2-2*smax,1e-12))/2 * mask[n1,p]; per-pair max over p
// ---------------------------------------------------------------------------
__global__ __launch_bounds__(256) void sp_kernel(const float* __restrict__ mask) {
    const int pair = blockIdx.x;
    const int n1 = (pair >> 3) & 7;
    const int tid = threadIdx.x;
    __shared__ float red[256];
    float m = -1.0f;
    for (int p = tid; p < PP; p += 256) {
        float s  = g_maxdot[pair * PP + p];
        float d2 = fmaxf(2.0f - 2.0f * s, 1e-12f);
        float sp = sqrtf(d2) * 0.5f * mask[n1 * PP + p];
        g_sp[pair * PP + p] = sp;
        m = fmaxf(m, sp);
    }
    red[tid] = m;
    __syncthreads();
    for (int s = 128; s > 0; s >>= 1) {
        if (tid < s) red[tid] = fmaxf(red[tid], red[tid + s]);
        __syncthreads();
    }
    if (tid == 0) g_maxp[pair] = red[0];
}

// ---------------------------------------------------------------------------
// Kernel 4: spbar[n1,p] = mean over (l,n2) of sp
// ---------------------------------------------------------------------------
__global__ __launch_bounds__(256) void spbar_kernel() {
    int idx = blockIdx.x * 256 + threadIdx.x;
    if (idx >= NN1 * PP) return;
    int n1 = idx >> 10;
    int p  = idx & (PP - 1);
    float s = 0.f;
#pragma unroll
    for (int l = 0; l < LL; l++)
#pragma unroll
        for (int n2 = 0; n2 < NN2; n2++)
            s += g_sp[(((size_t)l * NN1 + n1) * NN2 + n2) * PP + p];
    g_spbar[idx] = s * (1.0f / (LL * NN2));
}

// ---------------------------------------------------------------------------
// Kernel 5: scores[n1] = mean over (l,n2) of maxp -> out[0..7]
// ---------------------------------------------------------------------------
__global__ void scores_kernel(float* __restrict__ out) {
    int n1 = threadIdx.x;
    if (n1 < NN1) {
        float s = 0.f;
#pragma unroll
        for (int l = 0; l < LL; l++)
#pragma unroll
            for (int n2 = 0; n2 < NN2; n2++)
                s += g_maxp[(l * NN1 + n1) * NN2 + n2];
        out[n1] = s * (1.0f / (LL * NN2));
    }
}

// ---------------------------------------------------------------------------
// Kernel 6: bilinear resize 32x32 -> 512x512 (half-pixel centers, edge clamp)
// ---------------------------------------------------------------------------
__global__ __launch_bounds__(256) void resize_kernel(float* __restrict__ out) {
    int idx = blockIdx.x * 256 + threadIdx.x;
    if (idx >= NN1 * IMG * IMG) return;
    int n1  = idx >> 18;
    int rem = idx & (IMG * IMG - 1);
    int y = rem >> 9;
    int x = rem & (IMG - 1);

    float sy = (y + 0.5f) * (1.0f / 16.0f) - 0.5f;
    float sx = (x + 0.5f) * (1.0f / 16.0f) - 0.5f;
    int y0 = (int)floorf(sy);
    int x0 = (int)floorf(sx);
    float wy = sy - (float)y0;
    float wx = sx - (float)x0;
    int y0c = min(max(y0, 0), PH - 1);
    int y1c = min(max(y0 + 1, 0), PH - 1);
    int x0c = min(max(x0, 0), PW - 1);
    int x1c = min(max(x0 + 1, 0), PW - 1);

    const float* sb = g_spbar + n1 * PP;
    float v00 = sb[y0c * PW + x0c];
    float v01 = sb[y0c * PW + x1c];
    float v10 = sb[y1c * PW + x0c];
    float v11 = sb[y1c * PW + x1c];
    float v = (1.f - wy) * ((1.f - wx) * v00 + wx * v01)
            +        wy  * ((1.f - wx) * v10 + wx * v11);
    out[8 + idx] = v;
}

// ---------------------------------------------------------------------------
extern "C" void kernel_launch(void* const* d_in, const int* in_sizes, int n_in,
                              void* d_out, int out_size) {
    const float* feats  = (const float*)d_in[0];
    const float* nfeats = (const float*)d_in[1];
    const float* mask   = (const float*)d_in[2];
    float* out = (float*)d_out;

    const int rows = LL * NN1 * PP;  // 16384 rows per tensor

    dim3 ngrid(rows / 8, 2);
    normalize_kernel<<<ngrid, 256>>>(feats, nfeats, rows);

    cudaFuncSetAttribute(distmax_bf16_v3,
                         cudaFuncAttributeMaxDynamicSharedMemorySize, SMEM_BYTES);
    dim3 grid(PP / BM, LL * NN1 * NN2);  // (8, 128)
    distmax_bf16_v3<<<grid, 256, SMEM_BYTES>>>();

    sp_kernel<<<LL * NN1 * NN2, 256>>>(mask);
    spbar_kernel<<<(NN1 * PP + 255) / 256, 256>>>();
    scores_kernel<<<1, 32>>>(out);
    resize_kernel<<<(NN1 * IMG * IMG + 255) / 256, 256>>>(out);
}

// round 9
// speedup vs baseline: 1.5508x; 1.5508x over previous
#include <cuda_runtime.h>
#include <cuda_bf16.h>
#include <math.h>
#include <stdint.h>

#define LL 2
#define NN1 8
#define NN2 8
#define PP 1024
#define DD 768
#define PH 32
#define PW 32
#define IMG 512

// Scratch (device globals; no allocation allowed)
__device__ __nv_bfloat16 g_fa[LL * NN1 * PP * DD];  // normalized feats (bf16)
__device__ __nv_bfloat16 g_fb[LL * NN2 * PP * DD];  // normalized nfeats (bf16)
__device__ float g_maxdot[LL * NN1 * NN2 * PP];     // max_p2 cos-sim
__device__ float g_sp[LL * NN1 * NN2 * PP];
__device__ float g_maxp[LL * NN1 * NN2];
__device__ float g_spbar[NN1 * PP];

// ---------------------------------------------------------------------------
// Kernel 1: L2-normalize rows of [rows, 768] -> bf16. One warp per row.
// grid.y = 0 -> feats->g_fa, 1 -> nfeats->g_fb
// ---------------------------------------------------------------------------
__global__ __launch_bounds__(256) void normalize_kernel(const float* __restrict__ inA,
                                                        const float* __restrict__ inB,
                                                        int nrows) {
    int row  = blockIdx.x * 8 + (threadIdx.x >> 5);
    int lane = threadIdx.x & 31;
    if (row >= nrows) return;
    const float* in = blockIdx.y ? inB : inA;
    __nv_bfloat16* outbase = blockIdx.y ? g_fb : g_fa;
    const float4* src = (const float4*)(in + (size_t)row * DD);
    __nv_bfloat162* dst = (__nv_bfloat162*)(outbase + (size_t)row * DD);

    float4 v[6];
    float ss = 0.f;
#pragma unroll
    for (int i = 0; i < 6; i++) {
        v[i] = src[lane + 32 * i];
        ss += v[i].x * v[i].x + v[i].y * v[i].y + v[i].z * v[i].z + v[i].w * v[i].w;
    }
#pragma unroll
    for (int o = 16; o > 0; o >>= 1) ss += __shfl_xor_sync(0xffffffffu, ss, o);
    float inv = 1.0f / sqrtf(ss);
#pragma unroll
    for (int i = 0; i < 6; i++) {
        int e = lane + 32 * i;
        dst[e * 2 + 0] = __floats2bfloat162_rn(v[i].x * inv, v[i].y * inv);
        dst[e * 2 + 1] = __floats2bfloat162_rn(v[i].z * inv, v[i].w * inv);
    }
}

// ---------------------------------------------------------------------------
// Kernel 2: fused bf16 mma.sync GEMM + row-max (v4 = R7 config + 1 sync/stage).
// Pair = (l,n1,n2): S = A[1024,768]*B[1024,768]^T; keep row max over columns.
// Block: 128-row strip of A. Flat 96-stage pipeline over (8 col tiles x 12
// K-stages of 64). 256 thr = 8 warps (2m x 4n), warp tile 64x32,
// mma.m16n8k16.bf16, double-buffered cp.async (75.7KB smem -> 2 CTAs/SM),
// ONE __syncthreads per stage: wait -> sync -> issue(s+1) -> compute(s).
// ---------------------------------------------------------------------------
#define BM 128
#define BN 128
#define RSB 144               // smem row stride in bytes (128 + 16 pad)
#define ABUF (128 * RSB)      // one buffer of one matrix = 18432 B
#define OFF_B (2 * ABUF)      // 36864
#define OFF_PART (4 * ABUF)   // 73728
#define SMEM_BYTES (OFF_PART + 4 * 128 * 4)  // 75776

#define CP16(dst_u32, src_ptr) \
    asm volatile("cp.async.cg.shared.global [%0], [%1], 16;\n" :: "r"(dst_u32), "l"(src_ptr))

__device__ __forceinline__ void ldsm4(uint32_t* r, uint32_t addr) {
    asm volatile("ldmatrix.sync.aligned.m8n8.x4.shared.b16 {%0,%1,%2,%3}, [%4];"
                 : "=r"(r[0]), "=r"(r[1]), "=r"(r[2]), "=r"(r[3]) : "r"(addr));
}

__global__ __launch_bounds__(256, 2) void distmax_bf16_v4() {
    extern __shared__ char dsm[];
    uint32_t sm = (uint32_t)__cvta_generic_to_shared(dsm);
    float* part = (float*)(dsm + OFF_PART);

    const int pair = blockIdx.y;          // ((l*8 + n1)*8 + n2)
    const int l  = pair >> 6;
    const int n1 = (pair >> 3) & 7;
    const int n2 = pair & 7;
    const __nv_bfloat16* __restrict__ A =
        g_fa + (((size_t)(l * NN1 + n1)) * PP + blockIdx.x * BM) * DD;
    const __nv_bfloat16* __restrict__ B = g_fb + ((size_t)(l * NN2 + n2)) * PP * DD;

    const int tid  = threadIdx.x;
    const int lane = tid & 31;
    const int warp = tid >> 5;
    const int wm = warp >> 2;        // 0..1
    const int wn = warp & 3;         // 0..3
    const int g  = lane >> 2;        // 0..7
    const int t4 = lane & 3;         // 0..3
    const int sub = lane >> 3;       // 0..3 (ldmatrix sub-matrix)
    const int lr8 = lane & 7;

    // cp.async: 4 chunks per matrix per stage; each eighth-warp = one 128B row
    const int rB = tid >> 3;         // 0..31
    const int cc = tid & 7;          // 16B chunk within 128B row
    uint32_t dA[4], dB[4];
    const __nv_bfloat16 *aS[4], *bS[4];
#pragma unroll
    for (int i = 0; i < 4; i++) {
        int r = rB + 32 * i;
        dA[i] = sm + (uint32_t)(r * RSB + cc * 16);
        dB[i] = sm + OFF_B + (uint32_t)(r * RSB + cc * 16);
        aS[i] = A + (size_t)r * DD + cc * 8;
        bS[i] = B + (size_t)r * DD + cc * 8;
    }

    // ldmatrix per-lane byte offsets within a buffer (R4/R7-proven mapping):
    // A: rows from sub&1, k from sub>>1 ; B: rows from sub>>1, k from sub&1
    const uint32_t aLds = (uint32_t)((wm * 64 + (sub & 1) * 8 + lr8) * RSB +
                                     (sub >> 1) * 16);
    const uint32_t bLds = (uint32_t)((wn * 32 + (sub >> 1) * 8 + lr8) * RSB +
                                     (sub & 1) * 16);

    float rmax[4][2];
#pragma unroll
    for (int i = 0; i < 4; i++) { rmax[i][0] = -2.f; rmax[i][1] = -2.f; }

    // stage s = ct*12 + kstep ; issue() loads the next sequential stage
    int ct_n = 0, k_n = 0;   // (ct,k) of the NEXT stage to issue
    int ib = 0;              // buffer of the NEXT stage to issue
    auto issue = [&]() {
        uint32_t bo = (uint32_t)(ib * (2 * ABUF) ? 0 : 0);  // placeholder (unused)
        (void)bo;
        uint32_t bufo = (uint32_t)(ib * ABUF * 0);          // silence
        (void)bufo;
        uint32_t off = (uint32_t)(ib * 0);
        (void)off;
        // actual: buffers alternate at stride ABUF within each matrix region
        uint32_t sel = (uint32_t)(ib * ABUF);
        int ko = k_n * 64;
        size_t bco = (size_t)ct_n * BN * DD + ko;
#pragma unroll
        for (int i = 0; i < 4; i++) CP16(dA[i] + sel, aS[i] + ko);
#pragma unroll
        for (int i = 0; i < 4; i++) CP16(dB[i] + sel, bS[i] + bco);
        asm volatile("cp.async.commit_group;\n");
        if (++k_n == 12) { k_n = 0; ct_n++; }
        ib ^= 1;
    };

    issue();   // prime stage 0 into buffer 0

    float acc[4][4][4];
    int kc = 0;  // kstep of current stage

    for (int s = 0; s < 96; s++) {
        asm volatile("cp.async.wait_group 0;\n");   // stage s landed
        __syncthreads();                             // compute(s-1) fully done
        if (s + 1 < 96) issue();                     // overwrite buffer (s+1)&1

        if (kc == 0) {
#pragma unroll
            for (int mi = 0; mi < 4; mi++)
#pragma unroll
                for (int ni = 0; ni < 4; ni++)
#pragma unroll
                    for (int r = 0; r < 4; r++) acc[mi][ni][r] = 0.f;
        }

        const uint32_t sel = (uint32_t)((s & 1) * ABUF);
        const uint32_t aBuf = sm + sel;
        const uint32_t bBuf = sm + OFF_B + sel;

#pragma unroll
        for (int k16 = 0; k16 < 4; k16++) {
            uint32_t a[4][4], b[2][4];
#pragma unroll
            for (int mi = 0; mi < 4; mi++)
                ldsm4(a[mi], aBuf + aLds + (uint32_t)(mi * 16 * RSB + k16 * 32));
#pragma unroll
            for (int np = 0; np < 2; np++)
                ldsm4(b[np], bBuf + bLds + (uint32_t)(np * 16 * RSB + k16 * 32));
#pragma unroll
            for (int mi = 0; mi < 4; mi++)
#pragma unroll
                for (int ni = 0; ni < 4; ni++) {
                    asm volatile(
                        "mma.sync.aligned.m16n8k16.row.col.f32.bf16.bf16.f32 "
                        "{%0,%1,%2,%3},{%4,%5,%6,%7},{%8,%9},{%0,%1,%2,%3};\n"
                        : "+f"(acc[mi][ni][0]), "+f"(acc[mi][ni][1]),
                          "+f"(acc[mi][ni][2]), "+f"(acc[mi][ni][3])
                        : "r"(a[mi][0]), "r"(a[mi][1]), "r"(a[mi][2]), "r"(a[mi][3]),
                          "r"(b[ni >> 1][(ni & 1) * 2]), "r"(b[ni >> 1][(ni & 1) * 2 + 1]));
                }
        }

        if (kc == 11) {
            // column tile finished: fold into running row max
            // c0,c1 -> row g; c2,c3 -> row g+8
#pragma unroll
            for (int mi = 0; mi < 4; mi++) {
                float m0 = -2.f, m1 = -2.f;
#pragma unroll
                for (int ni = 0; ni < 4; ni++) {
                    m0 = fmaxf(m0, fmaxf(acc[mi][ni][0], acc[mi][ni][1]));
                    m1 = fmaxf(m1, fmaxf(acc[mi][ni][2], acc[mi][ni][3]));
                }
                rmax[mi][0] = fmaxf(rmax[mi][0], m0);
                rmax[mi][1] = fmaxf(rmax[mi][1], m1);
            }
            kc = 0;
        } else {
            kc++;
        }
    }

    // reduce across the 4 lanes sharing g (t4 = lane&3)
#pragma unroll
    for (int o = 1; o <= 2; o <<= 1) {
#pragma unroll
        for (int mi = 0; mi < 4; mi++) {
            rmax[mi][0] = fmaxf(rmax[mi][0], __shfl_xor_sync(0xffffffffu, rmax[mi][0], o));
            rmax[mi][1] = fmaxf(rmax[mi][1], __shfl_xor_sync(0xffffffffu, rmax[mi][1], o));
        }
    }
    if (t4 == 0) {
#pragma unroll
        for (int mi = 0; mi < 4; mi++) {
            int r = wm * 64 + mi * 16 + g;
            part[wn * 128 + r] = rmax[mi][0];
            part[wn * 128 + r + 8] = rmax[mi][1];
        }
    }
    __syncthreads();
    if (tid < 128) {
        float v = fmaxf(fmaxf(part[tid], part[128 + tid]),
                        fmaxf(part[256 + tid], part[384 + tid]));
        g_maxdot[(size_t)pair * PP + blockIdx.x * BM + tid] = v;
    }
}

// ---------------------------------------------------------------------------
// Kernel 3: sp = sqrt(max(2-2*smax,1e-12))/2 * mask[n1,p]; per-pair max over p
// ---------------------------------------------------------------------------
__global__ __launch_bounds__(256) void sp_kernel(const float* __restrict__ mask) {
    const int pair = blockIdx.x;
    const int n1 = (pair >> 3) & 7;
    const int tid = threadIdx.x;
    __shared__ float red[256];
    float m = -1.0f;
    for (int p = tid; p < PP; p += 256) {
        float s  = g_maxdot[pair * PP + p];
        float d2 = fmaxf(2.0f - 2.0f * s, 1e-12f);
        float sp = sqrtf(d2) * 0.5f * mask[n1 * PP + p];
        g_sp[pair * PP + p] = sp;
        m = fmaxf(m, sp);
    }
    red[tid] = m;
    __syncthreads();
    for (int s = 128; s > 0; s >>= 1) {
        if (tid < s) red[tid] = fmaxf(red[tid], red[tid + s]);
        __syncthreads();
    }
    if (tid == 0) g_maxp[pair] = red[0];
}

// ---------------------------------------------------------------------------
// Kernel 4: spbar[n1,p] = mean over (l,n2) of sp
// ---------------------------------------------------------------------------
__global__ __launch_bounds__(256) void spbar_kernel() {
    int idx = blockIdx.x * 256 + threadIdx.x;
    if (idx >= NN1 * PP) return;
    int n1 = idx >> 10;
    int p  = idx & (PP - 1);
    float s = 0.f;
#pragma unroll
    for (int l = 0; l < LL; l++)
#pragma unroll
        for (int n2 = 0; n2 < NN2; n2++)
            s += g_sp[(((size_t)l * NN1 + n1) * NN2 + n2) * PP + p];
    g_spbar[idx] = s * (1.0f / (LL * NN2));
}

// ---------------------------------------------------------------------------
// Kernel 5: scores[n1] = mean over (l,n2) of maxp -> out[0..7]
// ---------------------------------------------------------------------------
__global__ void scores_kernel(float* __restrict__ out) {
    int n1 = threadIdx.x;
    if (n1 < NN1) {
        float s = 0.f;
#pragma unroll
        for (int l = 0; l < LL; l++)
#pragma unroll
            for (int n2 = 0; n2 < NN2; n2++)
                s += g_maxp[(l * NN1 + n1) * NN2 + n2];
        out[n1] = s * (1.0f / (LL * NN2));
    }
}

// ---------------------------------------------------------------------------
// Kernel 6: bilinear resize 32x32 -> 512x512 (half-pixel centers, edge clamp)
// ---------------------------------------------------------------------------
__global__ __launch_bounds__(256) void resize_kernel(float* __restrict__ out) {
    int idx = blockIdx.x * 256 + threadIdx.x;
    if (idx >= NN1 * IMG * IMG) return;
    int n1  = idx >> 18;
    int rem = idx & (IMG * IMG - 1);
    int y = rem >> 9;
    int x = rem & (IMG - 1);

    float sy = (y + 0.5f) * (1.0f / 16.0f) - 0.5f;
    float sx = (x + 0.5f) * (1.0f / 16.0f) - 0.5f;
    int y0 = (int)floorf(sy);
    int x0 = (int)floorf(sx);
    float wy = sy - (float)y0;
    float wx = sx - (float)x0;
    int y0c = min(max(y0, 0), PH - 1);
    int y1c = min(max(y0 + 1, 0), PH - 1);
    int x0c = min(max(x0, 0), PW - 1);
    int x1c = min(max(x0 + 1, 0), PW - 1);

    const float* sb = g_spbar + n1 * PP;
    float v00 = sb[y0c * PW + x0c];
    float v01 = sb[y0c * PW + x1c];
    float v10 = sb[y1c * PW + x0c];
    float v11 = sb[y1c * PW + x1c];
    float v = (1.f - wy) * ((1.f - wx) * v00 + wx * v01)
            +        wy  * ((1.f - wx) * v10 + wx * v11);
    out[8 + idx] = v;
}

// ---------------------------------------------------------------------------
extern "C" void kernel_launch(void* const* d_in, const int* in_sizes, int n_in,
                              void* d_out, int out_size) {
    const float* feats  = (const float*)d_in[0];
    const float* nfeats = (const float*)d_in[1];
    const float* mask   = (const float*)d_in[2];
    float* out = (float*)d_out;

    const int rows = LL * NN1 * PP;  // 16384 rows per tensor

    dim3 ngrid(rows / 8, 2);
    normalize_kernel<<<ngrid, 256>>>(feats, nfeats, rows);

    cudaFuncSetAttribute(distmax_bf16_v4,
                         cudaFuncAttributeMaxDynamicSharedMemorySize, SMEM_BYTES);
    dim3 grid(PP / BM, LL * NN1 * NN2);  // (8, 128)
    distmax_bf16_v4<<<grid, 256, SMEM_BYTES>>>();

    sp_kernel<<<LL * NN1 * NN2, 256>>>(mask);
    spbar_kernel<<<(NN1 * PP + 255) / 256, 256>>>();
    scores_kernel<<<1, 32>>>(out);
    resize_kernel<<<(NN1 * IMG * IMG + 255) / 256, 256>>>(out);
}

// round 10
// speedup vs baseline: 1.5875x; 1.0237x over previous
#include <cuda_runtime.h>
#include <cuda_bf16.h>
#include <math.h>
#include <stdint.h>

#define LL 2
#define NN1 8
#define NN2 8
#define PP 1024
#define DD 768
#define PH 32
#define PW 32
#define IMG 512

// Scratch (device globals; no allocation allowed)
__device__ __nv_bfloat16 g_fa[LL * NN1 * PP * DD];  // normalized feats (bf16)
__device__ __nv_bfloat16 g_fb[LL * NN2 * PP * DD];  // normalized nfeats (bf16)
__device__ float g_md2[2 * LL * NN1 * NN2 * PP];    // per-column-half row max
__device__ float g_sp[LL * NN1 * NN2 * PP];
__device__ float g_maxp[LL * NN1 * NN2];
__device__ float g_spbar[NN1 * PP];

// ---------------------------------------------------------------------------
// Kernel 1: L2-normalize rows of [rows, 768] -> bf16. One warp per row.
// grid.y = 0 -> feats->g_fa, 1 -> nfeats->g_fb
// ---------------------------------------------------------------------------
__global__ __launch_bounds__(256) void normalize_kernel(const float* __restrict__ inA,
                                                        const float* __restrict__ inB,
                                                        int nrows) {
    int row  = blockIdx.x * 8 + (threadIdx.x >> 5);
    int lane = threadIdx.x & 31;
    if (row >= nrows) return;
    const float* in = blockIdx.y ? inB : inA;
    __nv_bfloat16* outbase = blockIdx.y ? g_fb : g_fa;
    const float4* src = (const float4*)(in + (size_t)row * DD);
    __nv_bfloat162* dst = (__nv_bfloat162*)(outbase + (size_t)row * DD);

    float4 v[6];
    float ss = 0.f;
#pragma unroll
    for (int i = 0; i < 6; i++) {
        v[i] = src[lane + 32 * i];
        ss += v[i].x * v[i].x + v[i].y * v[i].y + v[i].z * v[i].z + v[i].w * v[i].w;
    }
#pragma unroll
    for (int o = 16; o > 0; o >>= 1) ss += __shfl_xor_sync(0xffffffffu, ss, o);
    float inv = 1.0f / sqrtf(ss);
#pragma unroll
    for (int i = 0; i < 6; i++) {
        int e = lane + 32 * i;
        dst[e * 2 + 0] = __floats2bfloat162_rn(v[i].x * inv, v[i].y * inv);
        dst[e * 2 + 1] = __floats2bfloat162_rn(v[i].z * inv, v[i].w * inv);
    }
}

// ---------------------------------------------------------------------------
// Kernel 2: fused bf16 mma.sync GEMM + row-max (v5 = v4 + column-half split).
// Pair = (l,n1,n2): S = A[1024,768]*B[1024,768]^T; row max over a 512-col half.
// Grid (16,128): blockIdx.x = rowblock(8) x colhalf(2). Each CTA: 128-row strip
// of A x 4 column tiles of 128 = flat 48-stage pipeline (12 K-stages of 64
// per tile). 256 thr = 8 warps (2m x 4n), warp tile 64x32, mma.m16n8k16.bf16,
// double-buffered cp.async (75.7KB smem -> 2 CTAs/SM), ONE sync per stage.
// ---------------------------------------------------------------------------
#define BM 128
#define BN 128
#define RSB 144               // smem row stride in bytes (128 + 16 pad)
#define ABUF (128 * RSB)      // one buffer of one matrix = 18432 B
#define OFF_B (2 * ABUF)      // 36864
#define OFF_PART (4 * ABUF)   // 73728
#define SMEM_BYTES (OFF_PART + 4 * 128 * 4)  // 75776
#define NSTG 48               // 4 column tiles x 12 K-stages

#define CP16(dst_u32, src_ptr) \
    asm volatile("cp.async.cg.shared.global [%0], [%1], 16;\n" :: "r"(dst_u32), "l"(src_ptr))

__device__ __forceinline__ void ldsm4(uint32_t* r, uint32_t addr) {
    asm volatile("ldmatrix.sync.aligned.m8n8.x4.shared.b16 {%0,%1,%2,%3}, [%4];"
                 : "=r"(r[0]), "=r"(r[1]), "=r"(r[2]), "=r"(r[3]) : "r"(addr));
}

__global__ __launch_bounds__(256, 2) void distmax_bf16_v5() {
    extern __shared__ char dsm[];
    uint32_t sm = (uint32_t)__cvta_generic_to_shared(dsm);
    float* part = (float*)(dsm + OFF_PART);

    const int pair = blockIdx.y;          // ((l*8 + n1)*8 + n2)
    const int l  = pair >> 6;
    const int n1 = (pair >> 3) & 7;
    const int n2 = pair & 7;
    const int rowblk = blockIdx.x & 7;
    const int half   = blockIdx.x >> 3;   // 0 or 1: column tiles [half*4, half*4+4)
    const __nv_bfloat16* __restrict__ A =
        g_fa + (((size_t)(l * NN1 + n1)) * PP + rowblk * BM) * DD;
    const __nv_bfloat16* __restrict__ B = g_fb + ((size_t)(l * NN2 + n2)) * PP * DD;

    const int tid  = threadIdx.x;
    const int lane = tid & 31;
    const int warp = tid >> 5;
    const int wm = warp >> 2;        // 0..1
    const int wn = warp & 3;         // 0..3
    const int g  = lane >> 2;        // 0..7
    const int t4 = lane & 3;         // 0..3
    const int sub = lane >> 3;       // 0..3 (ldmatrix sub-matrix)
    const int lr8 = lane & 7;

    // cp.async: 4 chunks per matrix per stage; each eighth-warp = one 128B row
    const int rB = tid >> 3;         // 0..31
    const int cc = tid & 7;          // 16B chunk within 128B row
    uint32_t dA[4], dB[4];
    const __nv_bfloat16 *aS[4], *bS[4];
#pragma unroll
    for (int i = 0; i < 4; i++) {
        int r = rB + 32 * i;
        dA[i] = sm + (uint32_t)(r * RSB + cc * 16);
        dB[i] = sm + OFF_B + (uint32_t)(r * RSB + cc * 16);
        aS[i] = A + (size_t)r * DD + cc * 8;
        bS[i] = B + (size_t)r * DD + cc * 8;
    }

    // ldmatrix per-lane byte offsets within a buffer (proven mapping):
    // A: rows from sub&1, k from sub>>1 ; B: rows from sub>>1, k from sub&1
    const uint32_t aLds = (uint32_t)((wm * 64 + (sub & 1) * 8 + lr8) * RSB +
                                     (sub >> 1) * 16);
    const uint32_t bLds = (uint32_t)((wn * 32 + (sub >> 1) * 8 + lr8) * RSB +
                                     (sub & 1) * 16);

    float rmax[4][2];
#pragma unroll
    for (int i = 0; i < 4; i++) { rmax[i][0] = -2.f; rmax[i][1] = -2.f; }

    // stage s = (ct - ct0)*12 + kstep ; issue() loads the next sequential stage
    int ct_n = half * 4, k_n = 0;   // (ct,k) of the NEXT stage to issue
    int ib = 0;                     // buffer of the NEXT stage to issue
    auto issue = [&]() {
        uint32_t sel = (uint32_t)(ib * ABUF);
        int ko = k_n * 64;
        size_t bco = (size_t)ct_n * BN * DD + ko;
#pragma unroll
        for (int i = 0; i < 4; i++) CP16(dA[i] + sel, aS[i] + ko);
#pragma unroll
        for (int i = 0; i < 4; i++) CP16(dB[i] + sel, bS[i] + bco);
        asm volatile("cp.async.commit_group;\n");
        if (++k_n == 12) { k_n = 0; ct_n++; }
        ib ^= 1;
    };

    issue();   // prime stage 0 into buffer 0

    float acc[4][4][4];
    int kc = 0;  // kstep of current stage

    for (int s = 0; s < NSTG; s++) {
        asm volatile("cp.async.wait_group 0;\n");   // stage s landed
        __syncthreads();                             // compute(s-1) fully done
        if (s + 1 < NSTG) issue();                   // overwrite buffer (s+1)&1

        if (kc == 0) {
#pragma unroll
            for (int mi = 0; mi < 4; mi++)
#pragma unroll
                for (int ni = 0; ni < 4; ni++)
#pragma unroll
                    for (int r = 0; r < 4; r++) acc[mi][ni][r] = 0.f;
        }

        const uint32_t sel = (uint32_t)((s & 1) * ABUF);
        const uint32_t aBuf = sm + sel;
        const uint32_t bBuf = sm + OFF_B + sel;

#pragma unroll
        for (int k16 = 0; k16 < 4; k16++) {
            uint32_t a[4][4], b[2][4];
#pragma unroll
            for (int mi = 0; mi < 4; mi++)
                ldsm4(a[mi], aBuf + aLds + (uint32_t)(mi * 16 * RSB + k16 * 32));
#pragma unroll
            for (int np = 0; np < 2; np++)
                ldsm4(b[np], bBuf + bLds + (uint32_t)(np * 16 * RSB + k16 * 32));
#pragma unroll
            for (int mi = 0; mi < 4; mi++)
#pragma unroll
                for (int ni = 0; ni < 4; ni++) {
                    asm volatile(
                        "mma.sync.aligned.m16n8k16.row.col.f32.bf16.bf16.f32 "
                        "{%0,%1,%2,%3},{%4,%5,%6,%7},{%8,%9},{%0,%1,%2,%3};\n"
                        : "+f"(acc[mi][ni][0]), "+f"(acc[mi][ni][1]),
                          "+f"(acc[mi][ni][2]), "+f"(acc[mi][ni][3])
                        : "r"(a[mi][0]), "r"(a[mi][1]), "r"(a[mi][2]), "r"(a[mi][3]),
                          "r"(b[ni >> 1][(ni & 1) * 2]), "r"(b[ni >> 1][(ni & 1) * 2 + 1]));
                }
        }

        if (kc == 11) {
            // column tile finished: fold into running row max
            // c0,c1 -> row g; c2,c3 -> row g+8
#pragma unroll
            for (int mi = 0; mi < 4; mi++) {
                float m0 = -2.f, m1 = -2.f;
#pragma unroll
                for (int ni = 0; ni < 4; ni++) {
                    m0 = fmaxf(m0, fmaxf(acc[mi][ni][0], acc[mi][ni][1]));
                    m1 = fmaxf(m1, fmaxf(acc[mi][ni][2], acc[mi][ni][3]));
                }
                rmax[mi][0] = fmaxf(rmax[mi][0], m0);
                rmax[mi][1] = fmaxf(rmax[mi][1], m1);
            }
            kc = 0;
        } else {
            kc++;
        }
    }

    // reduce across the 4 lanes sharing g (t4 = lane&3)
#pragma unroll
    for (int o = 1; o <= 2; o <<= 1) {
#pragma unroll
        for (int mi = 0; mi < 4; mi++) {
            rmax[mi][0] = fmaxf(rmax[mi][0], __shfl_xor_sync(0xffffffffu, rmax[mi][0], o));
            rmax[mi][1] = fmaxf(rmax[mi][1], __shfl_xor_sync(0xffffffffu, rmax[mi][1], o));
        }
    }
    if (t4 == 0) {
#pragma unroll
        for (int mi = 0; mi < 4; mi++) {
            int r = wm * 64 + mi * 16 + g;
            part[wn * 128 + r] = rmax[mi][0];
            part[wn * 128 + r + 8] = rmax[mi][1];
        }
    }
    __syncthreads();
    if (tid < 128) {
        float v = fmaxf(fmaxf(part[tid], part[128 + tid]),
                        fmaxf(part[256 + tid], part[384 + tid]));
        g_md2[(size_t)half * (128 * PP) + (size_t)pair * PP + rowblk * BM + tid] = v;
    }
}

// ---------------------------------------------------------------------------
// Kernel 3: combine halves; sp = sqrt(max(2-2*smax,1e-12))/2 * mask;
// per-pair max over p
// ---------------------------------------------------------------------------
__global__ __launch_bounds__(256) void sp_kernel(const float* __restrict__ mask) {
    const int pair = blockIdx.x;
    const int n1 = (pair >> 3) & 7;
    const int tid = threadIdx.x;
    __shared__ float red[256];
    float m = -1.0f;
    for (int p = tid; p < PP; p += 256) {
        float s  = fmaxf(g_md2[pair * PP + p], g_md2[128 * PP + pair * PP + p]);
        float d2 = fmaxf(2.0f - 2.0f * s, 1e-12f);
        float sp = sqrtf(d2) * 0.5f * mask[n1 * PP + p];
        g_sp[pair * PP + p] = sp;
        m = fmaxf(m, sp);
    }
    red[tid] = m;
    __syncthreads();
    for (int s = 128; s > 0; s >>= 1) {
        if (tid < s) red[tid] = fmaxf(red[tid], red[tid + s]);
        __syncthreads();
    }
    if (tid == 0) g_maxp[pair] = red[0];
}

// ---------------------------------------------------------------------------
// Kernel 4: spbar[n1,p] = mean over (l,n2) of sp
// ---------------------------------------------------------------------------
__global__ __launch_bounds__(256) void spbar_kernel() {
    int idx = blockIdx.x * 256 + threadIdx.x;
    if (idx >= NN1 * PP) return;
    int n1 = idx >> 10;
    int p  = idx & (PP - 1);
    float s = 0.f;
#pragma unroll
    for (int l = 0; l < LL; l++)
#pragma unroll
        for (int n2 = 0; n2 < NN2; n2++)
            s += g_sp[(((size_t)l * NN1 + n1) * NN2 + n2) * PP + p];
    g_spbar[idx] = s * (1.0f / (LL * NN2));
}

// ---------------------------------------------------------------------------
// Kernel 5: scores[n1] = mean over (l,n2) of maxp -> out[0..7]
// ---------------------------------------------------------------------------
__global__ void scores_kernel(float* __restrict__ out) {
    int n1 = threadIdx.x;
    if (n1 < NN1) {
        float s = 0.f;
#pragma unroll
        for (int l = 0; l < LL; l++)
#pragma unroll
            for (int n2 = 0; n2 < NN2; n2++)
                s += g_maxp[(l * NN1 + n1) * NN2 + n2];
        out[n1] = s * (1.0f / (LL * NN2));
    }
}

// ---------------------------------------------------------------------------
// Kernel 6: bilinear resize 32x32 -> 512x512 (half-pixel centers, edge clamp)
// ---------------------------------------------------------------------------
__global__ __launch_bounds__(256) void resize_kernel(float* __restrict__ out) {
    int idx = blockIdx.x * 256 + threadIdx.x;
    if (idx >= NN1 * IMG * IMG) return;
    int n1  = idx >> 18;
    int rem = idx & (IMG * IMG - 1);
    int y = rem >> 9;
    int x = rem & (IMG - 1);

    float sy = (y + 0.5f) * (1.0f / 16.0f) - 0.5f;
    float sx = (x + 0.5f) * (1.0f / 16.0f) - 0.5f;
    int y0 = (int)floorf(sy);
    int x0 = (int)floorf(sx);
    float wy = sy - (float)y0;
    float wx = sx - (float)x0;
    int y0c = min(max(y0, 0), PH - 1);
    int y1c = min(max(y0 + 1, 0), PH - 1);
    int x0c = min(max(x0, 0), PW - 1);
    int x1c = min(max(x0 + 1, 0), PW - 1);

    const float* sb = g_spbar + n1 * PP;
    float v00 = sb[y0c * PW + x0c];
    float v01 = sb[y0c * PW + x1c];
    float v10 = sb[y1c * PW + x0c];
    float v11 = sb[y1c * PW + x1c];
    float v = (1.f - wy) * ((1.f - wx) * v00 + wx * v01)
            +        wy  * ((1.f - wx) * v10 + wx * v11);
    out[8 + idx] = v;
}

// ---------------------------------------------------------------------------
extern "C" void kernel_launch(void* const* d_in, const int* in_sizes, int n_in,
                              void* d_out, int out_size) {
    const float* feats  = (const float*)d_in[0];
    const float* nfeats = (const float*)d_in[1];
    const float* mask   = (const float*)d_in[2];
    float* out = (float*)d_out;

    const int rows = LL * NN1 * PP;  // 16384 rows per tensor

    dim3 ngrid(rows / 8, 2);
    normalize_kernel<<<ngrid, 256>>>(feats, nfeats, rows);

    cudaFuncSetAttribute(distmax_bf16_v5,
                         cudaFuncAttributeMaxDynamicSharedMemorySize, SMEM_BYTES);
    dim3 grid(16, LL * NN1 * NN2);  // (rowblk x colhalf, 128 pairs) = 2048 CTAs
    distmax_bf16_v5<<<grid, 256, SMEM_BYTES>>>();

    sp_kernel<<<LL * NN1 * NN2, 256>>>(mask);
    spbar_kernel<<<(NN1 * PP + 255) / 256, 256>>>();
    scores_kernel<<<1, 32>>>(out);
    resize_kernel<<<(NN1 * IMG * IMG + 255) / 256, 256>>>(out);
}

// round 11
// speedup vs baseline: 1.8041x; 1.1364x over previous
#include <cuda_runtime.h>
#include <cuda_bf16.h>
#include <math.h>
#include <stdint.h>

#define LL 2
#define NN1 8
#define NN2 8
#define PP 1024
#define DD 768
#define PH 32
#define PW 32
#define IMG 512

// Scratch (device globals; no allocation allowed)
__device__ __nv_bfloat16 g_fa[LL * NN1 * PP * DD];  // normalized feats (bf16)
__device__ __nv_bfloat16 g_fb[LL * NN2 * PP * DD];  // normalized nfeats (bf16)
__device__ float g_md2[2 * LL * NN1 * NN2 * PP];    // per-column-half row max
__device__ float g_sp[LL * NN1 * NN2 * PP];
__device__ float g_maxp[LL * NN1 * NN2];
__device__ float g_spbar[NN1 * PP];

// ---------------------------------------------------------------------------
// Kernel 1: L2-normalize rows of [rows, 768] -> bf16. One warp per row.
// ---------------------------------------------------------------------------
__global__ __launch_bounds__(256) void normalize_kernel(const float* __restrict__ inA,
                                                        const float* __restrict__ inB,
                                                        int nrows) {
    int row  = blockIdx.x * 8 + (threadIdx.x >> 5);
    int lane = threadIdx.x & 31;
    if (row >= nrows) return;
    const float* in = blockIdx.y ? inB : inA;
    __nv_bfloat16* outbase = blockIdx.y ? g_fb : g_fa;
    const float4* src = (const float4*)(in + (size_t)row * DD);
    __nv_bfloat162* dst = (__nv_bfloat162*)(outbase + (size_t)row * DD);

    float4 v[6];
    float ss = 0.f;
#pragma unroll
    for (int i = 0; i < 6; i++) {
        v[i] = src[lane + 32 * i];
        ss += v[i].x * v[i].x + v[i].y * v[i].y + v[i].z * v[i].z + v[i].w * v[i].w;
    }
#pragma unroll
    for (int o = 16; o > 0; o >>= 1) ss += __shfl_xor_sync(0xffffffffu, ss, o);
    float inv = 1.0f / sqrtf(ss);
#pragma unroll
    for (int i = 0; i < 6; i++) {
        int e = lane + 32 * i;
        dst[e * 2 + 0] = __floats2bfloat162_rn(v[i].x * inv, v[i].y * inv);
        dst[e * 2 + 1] = __floats2bfloat162_rn(v[i].z * inv, v[i].w * inv);
    }
}

// ---------------------------------------------------------------------------
// Kernel 2: fused bf16 mma.sync GEMM + row-max (v6 = v5 + SW128 swizzle +
// 3-slot ring with depth-2 prefetch; still 2 CTAs/SM).
// Grid (16,128): blockIdx.x = rowblock(8) x colhalf(2). Each CTA: 128-row
// strip of A x 4 column tiles of 128 = flat 48-stage pipeline (12 K-stages
// of 64 per tile). 256 thr = 8 warps (2m x 4n), warp tile 64x32,
// mma.m16n8k16.bf16. Swizzled 128B rows: chunk' = chunk ^ (row & 7).
// ---------------------------------------------------------------------------
#define BM 128
#define BN 128
#define ABUF 16384            // one matrix buffer: 128 rows x 128 B
#define SLOT (2 * ABUF)       // A+B per ring slot = 32768 B
#define OFF_PART (3 * SLOT)   // 98304
#define SMEM_BYTES (OFF_PART + 4 * 128 * 4)  // 100352
#define NSTG 48               // 4 column tiles x 12 K-stages

#define CP16(dst_u32, src_ptr) \
    asm volatile("cp.async.cg.shared.global [%0], [%1], 16;\n" :: "r"(dst_u32), "l"(src_ptr))

__device__ __forceinline__ void ldsm4(uint32_t* r, uint32_t addr) {
    asm volatile("ldmatrix.sync.aligned.m8n8.x4.shared.b16 {%0,%1,%2,%3}, [%4];"
                 : "=r"(r[0]), "=r"(r[1]), "=r"(r[2]), "=r"(r[3]) : "r"(addr));
}

__global__ __launch_bounds__(256, 2) void distmax_bf16_v6() {
    extern __shared__ char dsm[];
    uint32_t sm = (uint32_t)__cvta_generic_to_shared(dsm);
    float* part = (float*)(dsm + OFF_PART);

    const int pair = blockIdx.y;          // ((l*8 + n1)*8 + n2)
    const int l  = pair >> 6;
    const int n1 = (pair >> 3) & 7;
    const int n2 = pair & 7;
    const int rowblk = blockIdx.x & 7;
    const int half   = blockIdx.x >> 3;   // column tiles [half*4, half*4+4)
    const __nv_bfloat16* __restrict__ A =
        g_fa + (((size_t)(l * NN1 + n1)) * PP + rowblk * BM) * DD;
    const __nv_bfloat16* __restrict__ B = g_fb + ((size_t)(l * NN2 + n2)) * PP * DD;

    const int tid  = threadIdx.x;
    const int lane = tid & 31;
    const int warp = tid >> 5;
    const int wm = warp >> 2;        // 0..1
    const int wn = warp & 3;         // 0..3
    const int g  = lane >> 2;        // 0..7
    const int t4 = lane & 3;         // 0..3
    const int sub = lane >> 3;       // 0..3 (ldmatrix sub-matrix)
    const int lr8 = lane & 7;

    // cp.async: each eighth-warp writes one 128B row; swizzle chunk ^ (row&7)
    const int rB = tid >> 3;         // base row 0..31 (+32*i)
    const int cc = tid & 7;          // source 16B chunk
    const uint32_t cx = (uint32_t)(((cc ^ (rB & 7)) & 7) * 16);  // swizzled chunk byte
    uint32_t dA[4], dB[4];
    const __nv_bfloat16 *aS[4], *bS[4];
#pragma unroll
    for (int i = 0; i < 4; i++) {
        int r = rB + 32 * i;         // r&7 == rB&7
        dA[i] = sm + (uint32_t)(r * 128) + cx;
        dB[i] = sm + ABUF + (uint32_t)(r * 128) + cx;
        aS[i] = A + (size_t)r * DD + cc * 8;
        bS[i] = B + (size_t)r * DD + cc * 8;
    }

    // ldmatrix addressing (proven fragment map + swizzle):
    // A: row = wm*64 + (sub&1)*8 + lr8, chunk = (sub>>1) + 2*k16
    // B: row = wn*32 + (sub>>1)*8 + lr8, chunk = (sub&1) + 2*k16
    const uint32_t aRow = (uint32_t)((wm * 64 + (sub & 1) * 8 + lr8) * 128);
    const uint32_t bRow = (uint32_t)((wn * 32 + (sub >> 1) * 8 + lr8) * 128);
    uint32_t aCk[4], bCk[4];
#pragma unroll
    for (int k16 = 0; k16 < 4; k16++) {
        aCk[k16] = (uint32_t)(((((sub >> 1) + 2 * k16) ^ lr8) & 7) * 16);
        bCk[k16] = (uint32_t)(((((sub & 1) + 2 * k16) ^ lr8) & 7) * 16);
    }

    float rmax[4][2];
#pragma unroll
    for (int i = 0; i < 4; i++) { rmax[i][0] = -2.f; rmax[i][1] = -2.f; }

    // issue(): load next sequential stage into next ring slot
    int ct_n = half * 4, k_n = 0;
    int ib = 0;
    auto issue = [&]() {
        uint32_t sel = (uint32_t)(ib * SLOT);
        int ko = k_n * 64;
        size_t bco = (size_t)ct_n * BN * DD + ko;
#pragma unroll
        for (int i = 0; i < 4; i++) CP16(dA[i] + sel, aS[i] + ko);
#pragma unroll
        for (int i = 0; i < 4; i++) CP16(dB[i] + sel, bS[i] + bco);
        asm volatile("cp.async.commit_group;\n");
        if (++k_n == 12) { k_n = 0; ct_n++; }
        if (++ib == 3) ib = 0;
    };

    issue();   // stage 0
    issue();   // stage 1

    float acc[4][4][4];
    int kc = 0;   // kstep within current column tile
    int cb = 0;   // ring slot of current compute stage

    for (int s = 0; s < NSTG; s++) {
        if (s + 1 < NSTG) {
            asm volatile("cp.async.wait_group 1;\n");  // stage s landed
        } else {
            asm volatile("cp.async.wait_group 0;\n");
        }
        __syncthreads();                               // compute(s-1) done
        if (s + 2 < NSTG) issue();                     // fill slot (s-1)%3

        if (kc == 0) {
#pragma unroll
            for (int mi = 0; mi < 4; mi++)
#pragma unroll
                for (int ni = 0; ni < 4; ni++)
#pragma unroll
                    for (int r = 0; r < 4; r++) acc[mi][ni][r] = 0.f;
        }

        const uint32_t aBuf = sm + (uint32_t)(cb * SLOT);
        const uint32_t bBuf = aBuf + ABUF;

#pragma unroll
        for (int k16 = 0; k16 < 4; k16++) {
            uint32_t a[4][4], b[2][4];
#pragma unroll
            for (int mi = 0; mi < 4; mi++)
                ldsm4(a[mi], aBuf + aRow + (uint32_t)(mi * 2048) + aCk[k16]);
#pragma unroll
            for (int np = 0; np < 2; np++)
                ldsm4(b[np], bBuf + bRow + (uint32_t)(np * 2048) + bCk[k16]);
#pragma unroll
            for (int mi = 0; mi < 4; mi++)
#pragma unroll
                for (int ni = 0; ni < 4; ni++) {
                    asm volatile(
                        "mma.sync.aligned.m16n8k16.row.col.f32.bf16.bf16.f32 "
                        "{%0,%1,%2,%3},{%4,%5,%6,%7},{%8,%9},{%0,%1,%2,%3};\n"
                        : "+f"(acc[mi][ni][0]), "+f"(acc[mi][ni][1]),
                          "+f"(acc[mi][ni][2]), "+f"(acc[mi][ni][3])
                        : "r"(a[mi][0]), "r"(a[mi][1]), "r"(a[mi][2]), "r"(a[mi][3]),
                          "r"(b[ni >> 1][(ni & 1) * 2]), "r"(b[ni >> 1][(ni & 1) * 2 + 1]));
                }
        }

        if (kc == 11) {
            // column tile finished: fold into running row max
            // c0,c1 -> row g; c2,c3 -> row g+8
#pragma unroll
            for (int mi = 0; mi < 4; mi++) {
                float m0 = -2.f, m1 = -2.f;
#pragma unroll
                for (int ni = 0; ni < 4; ni++) {
                    m0 = fmaxf(m0, fmaxf(acc[mi][ni][0], acc[mi][ni][1]));
                    m1 = fmaxf(m1, fmaxf(acc[mi][ni][2], acc[mi][ni][3]));
                }
                rmax[mi][0] = fmaxf(rmax[mi][0], m0);
                rmax[mi][1] = fmaxf(rmax[mi][1], m1);
            }
            kc = 0;
        } else {
            kc++;
        }
        if (++cb == 3) cb = 0;
    }

    // reduce across the 4 lanes sharing g (t4 = lane&3)
#pragma unroll
    for (int o = 1; o <= 2; o <<= 1) {
#pragma unroll
        for (int mi = 0; mi < 4; mi++) {
            rmax[mi][0] = fmaxf(rmax[mi][0], __shfl_xor_sync(0xffffffffu, rmax[mi][0], o));
            rmax[mi][1] = fmaxf(rmax[mi][1], __shfl_xor_sync(0xffffffffu, rmax[mi][1], o));
        }
    }
    if (t4 == 0) {
#pragma unroll
        for (int mi = 0; mi < 4; mi++) {
            int r = wm * 64 + mi * 16 + g;
            part[wn * 128 + r] = rmax[mi][0];
            part[wn * 128 + r + 8] = rmax[mi][1];
        }
    }
    __syncthreads();
    if (tid < 128) {
        float v = fmaxf(fmaxf(part[tid], part[128 + tid]),
                        fmaxf(part[256 + tid], part[384 + tid]));
        g_md2[(size_t)half * (128 * PP) + (size_t)pair * PP + rowblk * BM + tid] = v;
    }
}

// ---------------------------------------------------------------------------
// Kernel 3: combine halves; sp = sqrt(max(2-2*smax,1e-12))/2 * mask;
// per-pair max over p
// ---------------------------------------------------------------------------
__global__ __launch_bounds__(256) void sp_kernel(const float* __restrict__ mask) {
    const int pair = blockIdx.x;
    const int n1 = (pair >> 3) & 7;
    const int tid = threadIdx.x;
    __shared__ float red[256];
    float m = -1.0f;
    for (int p = tid; p < PP; p += 256) {
        float s  = fmaxf(g_md2[pair * PP + p], g_md2[128 * PP + pair * PP + p]);
        float d2 = fmaxf(2.0f - 2.0f * s, 1e-12f);
        float sp = sqrtf(d2) * 0.5f * mask[n1 * PP + p];
        g_sp[pair * PP + p] = sp;
        m = fmaxf(m, sp);
    }
    red[tid] = m;
    __syncthreads();
    for (int s = 128; s > 0; s >>= 1) {
        if (tid < s) red[tid] = fmaxf(red[tid], red[tid + s]);
        __syncthreads();
    }
    if (tid == 0) g_maxp[pair] = red[0];
}

// ---------------------------------------------------------------------------
// Kernel 4: spbar[n1,p] = mean over (l,n2) of sp
// ---------------------------------------------------------------------------
__global__ __launch_bounds__(256) void spbar_kernel() {
    int idx = blockIdx.x * 256 + threadIdx.x;
    if (idx >= NN1 * PP) return;
    int n1 = idx >> 10;
    int p  = idx & (PP - 1);
    float s = 0.f;
#pragma unroll
    for (int l = 0; l < LL; l++)
#pragma unroll
        for (int n2 = 0; n2 < NN2; n2++)
            s += g_sp[(((size_t)l * NN1 + n1) * NN2 + n2) * PP + p];
    g_spbar[idx] = s * (1.0f / (LL * NN2));
}

// ---------------------------------------------------------------------------
// Kernel 5: scores[n1] = mean over (l,n2) of maxp -> out[0..7]
// ---------------------------------------------------------------------------
__global__ void scores_kernel(float* __restrict__ out) {
    int n1 = threadIdx.x;
    if (n1 < NN1) {
        float s = 0.f;
#pragma unroll
        for (int l = 0; l < LL; l++)
#pragma unroll
            for (int n2 = 0; n2 < NN2; n2++)
                s += g_maxp[(l * NN1 + n1) * NN2 + n2];
        out[n1] = s * (1.0f / (LL * NN2));
    }
}

// ---------------------------------------------------------------------------
// Kernel 6: bilinear resize 32x32 -> 512x512 (half-pixel centers, edge clamp)
// ---------------------------------------------------------------------------
__global__ __launch_bounds__(256) void resize_kernel(float* __restrict__ out) {
    int idx = blockIdx.x * 256 + threadIdx.x;
    if (idx >= NN1 * IMG * IMG) return;
    int n1  = idx >> 18;
    int rem = idx & (IMG * IMG - 1);
    int y = rem >> 9;
    int x = rem & (IMG - 1);

    float sy = (y + 0.5f) * (1.0f / 16.0f) - 0.5f;
    float sx = (x + 0.5f) * (1.0f / 16.0f) - 0.5f;
    int y0 = (int)floorf(sy);
    int x0 = (int)floorf(sx);
    float wy = sy - (float)y0;
    float wx = sx - (float)x0;
    int y0c = min(max(y0, 0), PH - 1);
    int y1c = min(max(y0 + 1, 0), PH - 1);
    int x0c = min(max(x0, 0), PW - 1);
    int x1c = min(max(x0 + 1, 0), PW - 1);

    const float* sb = g_spbar + n1 * PP;
    float v00 = sb[y0c * PW + x0c];
    float v01 = sb[y0c * PW + x1c];
    float v10 = sb[y1c * PW + x0c];
    float v11 = sb[y1c * PW + x1c];
    float v = (1.f - wy) * ((1.f - wx) * v00 + wx * v01)
            +        wy  * ((1.f - wx) * v10 + wx * v11);
    out[8 + idx] = v;
}

// ---------------------------------------------------------------------------
extern "C" void kernel_launch(void* const* d_in, const int* in_sizes, int n_in,
                              void* d_out, int out_size) {
    const float* feats  = (const float*)d_in[0];
    const float* nfeats = (const float*)d_in[1];
    const float* mask   = (const float*)d_in[2];
    float* out = (float*)d_out;

    const int rows = LL * NN1 * PP;  // 16384 rows per tensor

    dim3 ngrid(rows / 8, 2);
    normalize_kernel<<<ngrid, 256>>>(feats, nfeats, rows);

    cudaFuncSetAttribute(distmax_bf16_v6,
                         cudaFuncAttributeMaxDynamicSharedMemorySize, SMEM_BYTES);
    dim3 grid(16, LL * NN1 * NN2);  // (rowblk x colhalf, 128 pairs) = 2048 CTAs
    distmax_bf16_v6<<<grid, 256, SMEM_BYTES>>>();

    sp_kernel<<<LL * NN1 * NN2, 256>>>(mask);
    spbar_kernel<<<(NN1 * PP + 255) / 256, 256>>>();
    scores_kernel<<<1, 32>>>(out);
    resize_kernel<<<(NN1 * IMG * IMG + 255) / 256, 256>>>(out);
}

// round 13
// speedup vs baseline: 1.8118x; 1.0043x over previous
#include <cuda_runtime.h>
#include <cuda_bf16.h>
#include <math.h>
#include <stdint.h>

#define LL 2
#define NN1 8
#define NN2 8
#define PP 1024
#define DD 768
#define PH 32
#define PW 32
#define IMG 512

// Scratch (device globals; no allocation allowed)
__device__ __nv_bfloat16 g_fa[LL * NN1 * PP * DD];  // normalized feats (bf16)
__device__ __nv_bfloat16 g_fb[LL * NN2 * PP * DD];  // normalized nfeats (bf16)
__device__ float g_md2[2 * LL * NN1 * NN2 * PP];    // per-column-half row max
__device__ float g_spbar[NN1 * PP];

// ---------------------------------------------------------------------------
// Kernel 1: L2-normalize rows of [rows, 768] -> bf16. One warp per row.
// ---------------------------------------------------------------------------
__global__ __launch_bounds__(256) void normalize_kernel(const float* __restrict__ inA,
                                                        const float* __restrict__ inB,
                                                        int nrows) {
    int row  = blockIdx.x * 8 + (threadIdx.x >> 5);
    int lane = threadIdx.x & 31;
    if (row >= nrows) return;
    const float* in = blockIdx.y ? inB : inA;
    __nv_bfloat16* outbase = blockIdx.y ? g_fb : g_fa;
    const float4* src = (const float4*)(in + (size_t)row * DD);
    __nv_bfloat162* dst = (__nv_bfloat162*)(outbase + (size_t)row * DD);

    float4 v[6];
    float ss = 0.f;
#pragma unroll
    for (int i = 0; i < 6; i++) {
        v[i] = src[lane + 32 * i];
        ss += v[i].x * v[i].x + v[i].y * v[i].y + v[i].z * v[i].z + v[i].w * v[i].w;
    }
#pragma unroll
    for (int o = 16; o > 0; o >>= 1) ss += __shfl_xor_sync(0xffffffffu, ss, o);
    float inv = 1.0f / sqrtf(ss);
#pragma unroll
    for (int i = 0; i < 6; i++) {
        int e = lane + 32 * i;
        dst[e * 2 + 0] = __floats2bfloat162_rn(v[i].x * inv, v[i].y * inv);
        dst[e * 2 + 1] = __floats2bfloat162_rn(v[i].z * inv, v[i].w * inv);
    }
}

// ---------------------------------------------------------------------------
// Kernel 2: fused bf16 mma.sync GEMM + row-max (v6 ordering — PROVEN).
// Grid (16,128): blockIdx.x = rowblock(8) x colhalf(2). Each CTA: 128-row
// strip of A x 4 column tiles of 128 = flat 48-stage pipeline (12 K-stages
// of 64 per tile). 256 thr = 8 warps (2m x 4n), warp tile 64x32,
// mma.m16n8k16.bf16. SW128-swizzled 128B rows, 3-slot ring / depth-2
// prefetch, stage boundary: wait_group -> __syncthreads -> issue.
// 2 CTAs/SM.
// ---------------------------------------------------------------------------
#define BM 128
#define BN 128
#define ABUF 16384            // one matrix buffer: 128 rows x 128 B
#define SLOT (2 * ABUF)       // A+B per ring slot = 32768 B
#define OFF_PART (3 * SLOT)   // 98304
#define SMEM_BYTES (OFF_PART + 4 * 128 * 4)  // 100352
#define NSTG 48               // 4 column tiles x 12 K-stages

#define CP16(dst_u32, src_ptr) \
    asm volatile("cp.async.cg.shared.global [%0], [%1], 16;\n" :: "r"(dst_u32), "l"(src_ptr))

__device__ __forceinline__ void ldsm4(uint32_t* r, uint32_t addr) {
    asm volatile("ldmatrix.sync.aligned.m8n8.x4.shared.b16 {%0,%1,%2,%3}, [%4];"
                 : "=r"(r[0]), "=r"(r[1]), "=r"(r[2]), "=r"(r[3]) : "r"(addr));
}

__global__ __launch_bounds__(256, 2) void distmax_bf16_v8() {
    extern __shared__ char dsm[];
    uint32_t sm = (uint32_t)__cvta_generic_to_shared(dsm);
    float* part = (float*)(dsm + OFF_PART);

    const int pair = blockIdx.y;          // ((l*8 + n1)*8 + n2)
    const int l  = pair >> 6;
    const int n1 = (pair >> 3) & 7;
    const int n2 = pair & 7;
    const int rowblk = blockIdx.x & 7;
    const int half   = blockIdx.x >> 3;   // column tiles [half*4, half*4+4)
    const __nv_bfloat16* __restrict__ A =
        g_fa + (((size_t)(l * NN1 + n1)) * PP + rowblk * BM) * DD;
    const __nv_bfloat16* __restrict__ B = g_fb + ((size_t)(l * NN2 + n2)) * PP * DD;

    const int tid  = threadIdx.x;
    const int lane = tid & 31;
    const int warp = tid >> 5;
    const int wm = warp >> 2;        // 0..1
    const int wn = warp & 3;         // 0..3
    const int g  = lane >> 2;        // 0..7
    const int t4 = lane & 3;         // 0..3
    const int sub = lane >> 3;       // 0..3 (ldmatrix sub-matrix)
    const int lr8 = lane & 7;

    // cp.async: each eighth-warp writes one 128B row; swizzle chunk ^ (row&7)
    const int rB = tid >> 3;         // base row 0..31 (+32*i)
    const int cc = tid & 7;          // source 16B chunk
    const uint32_t cx = (uint32_t)(((cc ^ (rB & 7)) & 7) * 16);
    uint32_t dA[4], dB[4];
    const __nv_bfloat16 *aS[4], *bS[4];
#pragma unroll
    for (int i = 0; i < 4; i++) {
        int r = rB + 32 * i;         // r&7 == rB&7
        dA[i] = sm + (uint32_t)(r * 128) + cx;
        dB[i] = sm + ABUF + (uint32_t)(r * 128) + cx;
        aS[i] = A + (size_t)r * DD + cc * 8;
        bS[i] = B + (size_t)r * DD + cc * 8;
    }

    // ldmatrix addressing (proven fragment map + swizzle):
    const uint32_t aRow = (uint32_t)((wm * 64 + (sub & 1) * 8 + lr8) * 128);
    const uint32_t bRow = (uint32_t)((wn * 32 + (sub >> 1) * 8 + lr8) * 128);
    uint32_t aCk[4], bCk[4];
#pragma unroll
    for (int k16 = 0; k16 < 4; k16++) {
        aCk[k16] = (uint32_t)(((((sub >> 1) + 2 * k16) ^ lr8) & 7) * 16);
        bCk[k16] = (uint32_t)(((((sub & 1) + 2 * k16) ^ lr8) & 7) * 16);
    }

    float rmax[4][2];
#pragma unroll
    for (int i = 0; i < 4; i++) { rmax[i][0] = -2.f; rmax[i][1] = -2.f; }

    // issue(): load next sequential stage into next ring slot
    int ct_n = half * 4, k_n = 0;
    int ib = 0;
    auto issue = [&]() {
        uint32_t sel = (uint32_t)(ib * SLOT);
        int ko = k_n * 64;
        size_t bco = (size_t)ct_n * BN * DD + ko;
#pragma unroll
        for (int i = 0; i < 4; i++) CP16(dA[i] + sel, aS[i] + ko);
#pragma unroll
        for (int i = 0; i < 4; i++) CP16(dB[i] + sel, bS[i] + bco);
        asm volatile("cp.async.commit_group;\n");
        if (++k_n == 12) { k_n = 0; ct_n++; }
        if (++ib == 3) ib = 0;
    };

    issue();   // stage 0
    issue();   // stage 1

    float acc[4][4][4];
    int kc = 0;   // kstep within current column tile
    int cb = 0;   // ring slot of current compute stage

    for (int s = 0; s < NSTG; s++) {
        if (s + 1 < NSTG) {
            asm volatile("cp.async.wait_group 1;\n");  // own stage-s group done
        } else {
            asm volatile("cp.async.wait_group 0;\n");
        }
        __syncthreads();                               // cross-thread visibility
        if (s + 2 < NSTG) issue();                     // fill slot (s-1)%3

        if (kc == 0) {
#pragma unroll
            for (int mi = 0; mi < 4; mi++)
#pragma unroll
                for (int ni = 0; ni < 4; ni++)
#pragma unroll
                    for (int r = 0; r < 4; r++) acc[mi][ni][r] = 0.f;
        }

        const uint32_t aBuf = sm + (uint32_t)(cb * SLOT);
        const uint32_t bBuf = aBuf + ABUF;

#pragma unroll
        for (int k16 = 0; k16 < 4; k16++) {
            uint32_t a[4][4], b[2][4];
#pragma unroll
            for (int mi = 0; mi < 4; mi++)
                ldsm4(a[mi], aBuf + aRow + (uint32_t)(mi * 2048) + aCk[k16]);
#pragma unroll
            for (int np = 0; np < 2; np++)
                ldsm4(b[np], bBuf + bRow + (uint32_t)(np * 2048) + bCk[k16]);
#pragma unroll
            for (int mi = 0; mi < 4; mi++)
#pragma unroll
                for (int ni = 0; ni < 4; ni++) {
                    asm volatile(
                        "mma.sync.aligned.m16n8k16.row.col.f32.bf16.bf16.f32 "
                        "{%0,%1,%2,%3},{%4,%5,%6,%7},{%8,%9},{%0,%1,%2,%3};\n"
                        : "+f"(acc[mi][ni][0]), "+f"(acc[mi][ni][1]),
                          "+f"(acc[mi][ni][2]), "+f"(acc[mi][ni][3])
                        : "r"(a[mi][0]), "r"(a[mi][1]), "r"(a[mi][2]), "r"(a[mi][3]),
                          "r"(b[ni >> 1][(ni & 1) * 2]), "r"(b[ni >> 1][(ni & 1) * 2 + 1]));
                }
        }

        if (kc == 11) {
            // column tile finished: fold into running row max
#pragma unroll
            for (int mi = 0; mi < 4; mi++) {
                float m0 = -2.f, m1 = -2.f;
#pragma unroll
                for (int ni = 0; ni < 4; ni++) {
                    m0 = fmaxf(m0, fmaxf(acc[mi][ni][0], acc[mi][ni][1]));
                    m1 = fmaxf(m1, fmaxf(acc[mi][ni][2], acc[mi][ni][3]));
                }
                rmax[mi][0] = fmaxf(rmax[mi][0], m0);
                rmax[mi][1] = fmaxf(rmax[mi][1], m1);
            }
            kc = 0;
        } else {
            kc++;
        }
        if (++cb == 3) cb = 0;
    }

    // reduce across the 4 lanes sharing g (t4 = lane&3)
#pragma unroll
    for (int o = 1; o <= 2; o <<= 1) {
#pragma unroll
        for (int mi = 0; mi < 4; mi++) {
            rmax[mi][0] = fmaxf(rmax[mi][0], __shfl_xor_sync(0xffffffffu, rmax[mi][0], o));
            rmax[mi][1] = fmaxf(rmax[mi][1], __shfl_xor_sync(0xffffffffu, rmax[mi][1], o));
        }
    }
    if (t4 == 0) {
#pragma unroll
        for (int mi = 0; mi < 4; mi++) {
            int r = wm * 64 + mi * 16 + g;
            part[wn * 128 + r] = rmax[mi][0];
            part[wn * 128 + r + 8] = rmax[mi][1];
        }
    }
    __syncthreads();
    if (tid < 128) {
        float v = fmaxf(fmaxf(part[tid], part[128 + tid]),
                        fmaxf(part[256 + tid], part[384 + tid]));
        g_md2[(size_t)half * (128 * PP) + (size_t)pair * PP + rowblk * BM + tid] = v;
    }
}

// ---------------------------------------------------------------------------
// Kernel 3 (fused): per n1: combine halves, sp, spbar, per-pair max over p,
// scores -> out[0..7]. One block per n1, 1024 threads (one per p).
// ---------------------------------------------------------------------------
__global__ __launch_bounds__(1024) void spfused_kernel(const float* __restrict__ mask,
                                                       float* __restrict__ out) {
    const int n1 = blockIdx.x;
    const int p  = threadIdx.x;
    const int lane = p & 31;
    const int warp = p >> 5;
    __shared__ float wmax[32][16];
    __shared__ float score[16];

    float mk = mask[n1 * PP + p];
    float sum = 0.f;
    float sps[16];
#pragma unroll
    for (int l = 0; l < LL; l++)
#pragma unroll
        for (int n2 = 0; n2 < NN2; n2++) {
            int w = l * NN2 + n2;
            int pr = (l * NN1 + n1) * NN2 + n2;
            float s = fmaxf(g_md2[pr * PP + p], g_md2[128 * PP + pr * PP + p]);
            float d2 = fmaxf(2.0f - 2.0f * s, 1e-12f);
            float sp = sqrtf(d2) * 0.5f * mk;
            sum += sp;
            sps[w] = sp;
        }
    g_spbar[n1 * PP + p] = sum * (1.0f / 16.0f);

    // per-pair max over p: warp shfl reduce, then cross-warp via shared
#pragma unroll
    for (int o = 16; o > 0; o >>= 1)
#pragma unroll
        for (int w = 0; w < 16; w++)
            sps[w] = fmaxf(sps[w], __shfl_xor_sync(0xffffffffu, sps[w], o));
    if (lane == 0)
#pragma unroll
        for (int w = 0; w < 16; w++) wmax[warp][w] = sps[w];
    __syncthreads();

    if (warp < 16) {
        float m = wmax[lane][warp];   // 32 warp-maxes of pair `warp`
#pragma unroll
        for (int o = 16; o > 0; o >>= 1)
            m = fmaxf(m, __shfl_xor_sync(0xffffffffu, m, o));
        if (lane == 0) score[warp] = m;
    }
    __syncthreads();
    if (p == 0) {
        float s = 0.f;
#pragma unroll
        for (int w = 0; w < 16; w++) s += score[w];
        out[n1] = s * (1.0f / 16.0f);
    }
}

// ---------------------------------------------------------------------------
// Kernel 4: bilinear resize 32x32 -> 512x512 (half-pixel centers, edge clamp)
// ---------------------------------------------------------------------------
__global__ __launch_bounds__(256) void resize_kernel(float* __restrict__ out) {
    int idx = blockIdx.x * 256 + threadIdx.x;
    if (idx >= NN1 * IMG * IMG) return;
    int n1  = idx >> 18;
    int rem = idx & (IMG * IMG - 1);
    int y = rem >> 9;
    int x = rem & (IMG - 1);

    float sy = (y + 0.5f) * (1.0f / 16.0f) - 0.5f;
    float sx = (x + 0.5f) * (1.0f / 16.0f) - 0.5f;
    int y0 = (int)floorf(sy);
    int x0 = (int)floorf(sx);
    float wy = sy - (float)y0;
    float wx = sx - (float)x0;
    int y0c = min(max(y0, 0), PH - 1);
    int y1c = min(max(y0 + 1, 0), PH - 1);
    int x0c = min(max(x0, 0), PW - 1);
    int x1c = min(max(x0 + 1, 0), PW - 1);

    const float* sb = g_spbar + n1 * PP;
    float v00 = sb[y0c * PW + x0c];
    float v01 = sb[y0c * PW + x1c];
    float v10 = sb[y1c * PW + x0c];
    float v11 = sb[y1c * PW + x1c];
    float v = (1.f - wy) * ((1.f - wx) * v00 + wx * v01)
            +        wy  * ((1.f - wx) * v10 + wx * v11);
    out[8 + idx] = v;
}

// ---------------------------------------------------------------------------
extern "C" void kernel_launch(void* const* d_in, const int* in_sizes, int n_in,
                              void* d_out, int out_size) {
    const float* feats  = (const float*)d_in[0];
    const float* nfeats = (const float*)d_in[1];
    const float* mask   = (const float*)d_in[2];
    float* out = (float*)d_out;

    const int rows = LL * NN1 * PP;  // 16384 rows per tensor

    dim3 ngrid(rows / 8, 2);
    normalize_kernel<<<ngrid, 256>>>(feats, nfeats, rows);

    cudaFuncSetAttribute(distmax_bf16_v8,
                         cudaFuncAttributeMaxDynamicSharedMemorySize, SMEM_BYTES);
    dim3 grid(16, LL * NN1 * NN2);  // (rowblk x colhalf, 128 pairs) = 2048 CTAs
    distmax_bf16_v8<<<grid, 256, SMEM_BYTES>>>();

    spfused_kernel<<<NN1, 1024>>>(mask, out);
    resize_kernel<<<(NN1 * IMG * IMG + 255) / 256, 256>>>(out);
}

// round 14
// speedup vs baseline: 1.9755x; 1.0903x over previous
#include <cuda_runtime.h>
#include <cuda_bf16.h>
#include <math.h>
#include <stdint.h>

#define LL 2
#define NN1 8
#define NN2 8
#define PP 1024
#define DD 768
#define PH 32
#define PW 32
#define IMG 512

// Blocked-swizzled bf16 storage: per matrix (1024x768): 8 rowblocks x 12
// kblocks of contiguous 16KB tiles; tile interior = 128 rows x 8 chunks of
// 16B with chunk' = chunk ^ (row & 7). Matrix stride = 96 tiles = 1.5 MB.
#define TILE_B 16384
#define MAT_B (96 * TILE_B)   // 1572864 bytes

__device__ __nv_bfloat16 g_fa[LL * NN1 * PP * DD];  // blocked-swizzled
__device__ __nv_bfloat16 g_fb[LL * NN2 * PP * DD];  // blocked-swizzled
__device__ float g_md2[2 * LL * NN1 * NN2 * PP];    // per-column-half row max
__device__ float g_spbar[NN1 * PP];

// ---------------------------------------------------------------------------
// Kernel 1: L2-normalize rows of [rows, 768] -> bf16 in blocked-swizzled
// layout. One warp per row; lane handles chunks c = lane, lane+32, lane+64.
// ---------------------------------------------------------------------------
__global__ __launch_bounds__(256) void normalize_kernel(const float* __restrict__ inA,
                                                        const float* __restrict__ inB,
                                                        int nrows) {
    int row  = blockIdx.x * 8 + (threadIdx.x >> 5);
    int lane = threadIdx.x & 31;
    if (row >= nrows) return;
    const float* in = blockIdx.y ? inB : inA;
    char* outb = (char*)(blockIdx.y ? g_fb : g_fa);
    const float4* src = (const float4*)(in + (size_t)row * DD);

    // chunk c = lane + 32*i holds elements [8c, 8c+8) = float4 idx 2c, 2c+1
    float4 v[6];
    float ss = 0.f;
#pragma unroll
    for (int i = 0; i < 3; i++) {
        v[2 * i + 0] = src[2 * lane + 64 * i];
        v[2 * i + 1] = src[2 * lane + 64 * i + 1];
        ss += v[2*i].x * v[2*i].x + v[2*i].y * v[2*i].y
            + v[2*i].z * v[2*i].z + v[2*i].w * v[2*i].w;
        ss += v[2*i+1].x * v[2*i+1].x + v[2*i+1].y * v[2*i+1].y
            + v[2*i+1].z * v[2*i+1].z + v[2*i+1].w * v[2*i+1].w;
    }
#pragma unroll
    for (int o = 16; o > 0; o >>= 1) ss += __shfl_xor_sync(0xffffffffu, ss, o);
    float inv = 1.0f / sqrtf(ss);

    const int rm = row & (PP - 1);       // row within matrix
    const size_t matoff = (size_t)(row >> 10) * MAT_B;
    const int r7 = rm & 127;
    const uint32_t inner = (uint32_t)(r7 * 128);

#pragma unroll
    for (int i = 0; i < 3; i++) {
        int c = lane + 32 * i;
        __nv_bfloat162 h0 = __floats2bfloat162_rn(v[2*i].x * inv,   v[2*i].y * inv);
        __nv_bfloat162 h1 = __floats2bfloat162_rn(v[2*i].z * inv,   v[2*i].w * inv);
        __nv_bfloat162 h2 = __floats2bfloat162_rn(v[2*i+1].x * inv, v[2*i+1].y * inv);
        __nv_bfloat162 h3 = __floats2bfloat162_rn(v[2*i+1].z * inv, v[2*i+1].w * inv);
        uint4 u;
        u.x = *(uint32_t*)&h0; u.y = *(uint32_t*)&h1;
        u.z = *(uint32_t*)&h2; u.w = *(uint32_t*)&h3;
        size_t addr = matoff
                    + ((size_t)((rm >> 7) * 12 + (c >> 3)) << 14)
                    + inner
                    + (uint32_t)((((c & 7) ^ (r7 & 7)) & 7) << 4);
        *(uint4*)(outb + addr) = u;
    }
}

// ---------------------------------------------------------------------------
// Kernel 2: fused bf16 mma.sync GEMM + row-max (v9 = bulk-TMA pipeline).
// Grid (16,128): blockIdx.x = rowblock(8) x colhalf(2). Each CTA: 128-row
// strip of A x 4 column tiles of 128 = flat 48-stage pipeline. Per stage:
// ONE thread issues 2 x 16KB cp.async.bulk into a 3-slot ring guarded by
// mbarriers (expect_tx 32KB). Stage boundary: sync -> issue -> mbar-wait
// (acquire gives cross-thread visibility). 256 thr = 8 warps (2m x 4n),
// warp tile 64x32, mma.m16n8k16.bf16, 2 CTAs/SM.
// ---------------------------------------------------------------------------
#define BM 128
#define BN 128
#define ABUF 16384            // A tile in slot
#define SLOT (2 * ABUF)       // A+B per ring slot = 32768 B
#define OFF_PART (3 * SLOT)   // 98304
#define SMEM_BYTES (OFF_PART + 4 * 128 * 4)  // 100352
#define NSTG 48               // 4 column tiles x 12 K-stages

__device__ __forceinline__ void ldsm4(uint32_t* r, uint32_t addr) {
    asm volatile("ldmatrix.sync.aligned.m8n8.x4.shared.b16 {%0,%1,%2,%3}, [%4];"
                 : "=r"(r[0]), "=r"(r[1]), "=r"(r[2]), "=r"(r[3]) : "r"(addr));
}

__device__ __forceinline__ void mbar_wait(uint32_t addr, int parity) {
    asm volatile(
        "{\n\t"
        ".reg .pred P1;\n\t"
        "WL_%=:\n\t"
        "mbarrier.try_wait.parity.acquire.cta.shared::cta.b64 P1, [%0], %1, 0x989680;\n\t"
        "@P1 bra.uni WD_%=;\n\t"
        "bra.uni WL_%=;\n\t"
        "WD_%=:\n\t"
        "}"
        :: "r"(addr), "r"(parity) : "memory");
}

__global__ __launch_bounds__(256, 2) void distmax_bf16_v9() {
    extern __shared__ char dsm[];
    __shared__ __align__(8) uint64_t mbar_s[3];
    uint32_t sm = (uint32_t)__cvta_generic_to_shared(dsm);
    uint32_t mb = (uint32_t)__cvta_generic_to_shared(mbar_s);
    float* part = (float*)(dsm + OFF_PART);

    const int pair = blockIdx.y;          // ((l*8 + n1)*8 + n2)
    const int l  = pair >> 6;
    const int n1 = (pair >> 3) & 7;
    const int n2 = pair & 7;
    const int rowblk = blockIdx.x & 7;
    const int half   = blockIdx.x >> 3;   // column tiles [half*4, half*4+4)
    const char* Abase = (const char*)g_fa + (size_t)(l * NN1 + n1) * MAT_B;
    const char* Bbase = (const char*)g_fb + (size_t)(l * NN2 + n2) * MAT_B;

    const int tid  = threadIdx.x;
    const int lane = tid & 31;
    const int warp = tid >> 5;
    const int wm = warp >> 2;        // 0..1
    const int wn = warp & 3;         // 0..3
    const int g  = lane >> 2;        // 0..7
    const int t4 = lane & 3;         // 0..3
    const int sub = lane >> 3;       // 0..3 (ldmatrix sub-matrix)
    const int lr8 = lane & 7;

    if (tid == 0) {
#pragma unroll
        for (int j = 0; j < 3; j++)
            asm volatile("mbarrier.init.shared.b64 [%0], %1;"
                         :: "r"(mb + 8 * j), "r"(1) : "memory");
    }
    __syncthreads();

    // ldmatrix addressing (proven fragment map + swizzle):
    const uint32_t aRow = (uint32_t)((wm * 64 + (sub & 1) * 8 + lr8) * 128);
    const uint32_t bRow = (uint32_t)((wn * 32 + (sub >> 1) * 8 + lr8) * 128);
    uint32_t aCk[4], bCk[4];
#pragma unroll
    for (int k16 = 0; k16 < 4; k16++) {
        aCk[k16] = (uint32_t)(((((sub >> 1) + 2 * k16) ^ lr8) & 7) * 16);
        bCk[k16] = (uint32_t)(((((sub & 1) + 2 * k16) ^ lr8) & 7) * 16);
    }

    float rmax[4][2];
#pragma unroll
    for (int i = 0; i < 4; i++) { rmax[i][0] = -2.f; rmax[i][1] = -2.f; }

    // issue(): one thread bulk-copies the next stage's A+B tiles.
    int ct_n = half * 4, k_n = 0;
    int ib = 0;
    auto issue = [&]() {
        if (tid == 0) {
            uint32_t bar = mb + (uint32_t)(ib * 8);
            uint32_t dst = sm + (uint32_t)(ib * SLOT);
            const char* asrc = Abase + ((size_t)(rowblk * 12 + k_n) << 14);
            const char* bsrc = Bbase + ((size_t)(ct_n * 12 + k_n) << 14);
            asm volatile("fence.proxy.async.shared::cta;" ::: "memory");
            asm volatile("mbarrier.arrive.expect_tx.shared.b64 _, [%0], %1;"
                         :: "r"(bar), "r"(2 * ABUF) : "memory");
            asm volatile(
                "cp.async.bulk.shared::cluster.global.mbarrier::complete_tx::bytes "
                "[%0], [%1], %2, [%3];"
                :: "r"(dst), "l"(asrc), "r"(ABUF), "r"(bar) : "memory");
            asm volatile(
                "cp.async.bulk.shared::cluster.global.mbarrier::complete_tx::bytes "
                "[%0], [%1], %2, [%3];"
                :: "r"(dst + ABUF), "l"(bsrc), "r"(ABUF), "r"(bar) : "memory");
        }
        if (++k_n == 12) { k_n = 0; ct_n++; }
        if (++ib == 3) ib = 0;
    };

    issue();   // stage 0
    issue();   // stage 1

    float acc[4][4][4];
    int kc = 0;   // kstep within current column tile
    int cb = 0;   // ring slot of current compute stage

    for (int s = 0; s < NSTG; s++) {
        // Barrier: all warps finished compute(s-1) -> safe to overwrite
        // slot (s-1)%3 == (s+2)%3.
        __syncthreads();
        if (s + 2 < NSTG) issue();
        // Acquire-wait: stage-s data visible to ALL threads.
        mbar_wait(mb + (uint32_t)(cb * 8), (s / 3) & 1);

        if (kc == 0) {
#pragma unroll
            for (int mi = 0; mi < 4; mi++)
#pragma unroll
                for (int ni = 0; ni < 4; ni++)
#pragma unroll
                    for (int r = 0; r < 4; r++) acc[mi][ni][r] = 0.f;
        }

        const uint32_t aBuf = sm + (uint32_t)(cb * SLOT);
        const uint32_t bBuf = aBuf + ABUF;

#pragma unroll
        for (int k16 = 0; k16 < 4; k16++) {
            uint32_t a[4][4], b[2][4];
#pragma unroll
            for (int mi = 0; mi < 4; mi++)
                ldsm4(a[mi], aBuf + aRow + (uint32_t)(mi * 2048) + aCk[k16]);
#pragma unroll
            for (int np = 0; np < 2; np++)
                ldsm4(b[np], bBuf + bRow + (uint32_t)(np * 2048) + bCk[k16]);
#pragma unroll
            for (int mi = 0; mi < 4; mi++)
#pragma unroll
                for (int ni = 0; ni < 4; ni++) {
                    asm volatile(
                        "mma.sync.aligned.m16n8k16.row.col.f32.bf16.bf16.f32 "
                        "{%0,%1,%2,%3},{%4,%5,%6,%7},{%8,%9},{%0,%1,%2,%3};\n"
                        : "+f"(acc[mi][ni][0]), "+f"(acc[mi][ni][1]),
                          "+f"(acc[mi][ni][2]), "+f"(acc[mi][ni][3])
                        : "r"(a[mi][0]), "r"(a[mi][1]), "r"(a[mi][2]), "r"(a[mi][3]),
                          "r"(b[ni >> 1][(ni & 1) * 2]), "r"(b[ni >> 1][(ni & 1) * 2 + 1]));
                }
        }

        if (kc == 11) {
            // column tile finished: fold into running row max
#pragma unroll
            for (int mi = 0; mi < 4; mi++) {
                float m0 = -2.f, m1 = -2.f;
#pragma unroll
                for (int ni = 0; ni < 4; ni++) {
                    m0 = fmaxf(m0, fmaxf(acc[mi][ni][0], acc[mi][ni][1]));
                    m1 = fmaxf(m1, fmaxf(acc[mi][ni][2], acc[mi][ni][3]));
                }
                rmax[mi][0] = fmaxf(rmax[mi][0], m0);
                rmax[mi][1] = fmaxf(rmax[mi][1], m1);
            }
            kc = 0;
        } else {
            kc++;
        }
        if (++cb == 3) cb = 0;
    }

    // reduce across the 4 lanes sharing g (t4 = lane&3)
#pragma unroll
    for (int o = 1; o <= 2; o <<= 1) {
#pragma unroll
        for (int mi = 0; mi < 4; mi++) {
            rmax[mi][0] = fmaxf(rmax[mi][0], __shfl_xor_sync(0xffffffffu, rmax[mi][0], o));
            rmax[mi][1] = fmaxf(rmax[mi][1], __shfl_xor_sync(0xffffffffu, rmax[mi][1], o));
        }
    }
    if (t4 == 0) {
#pragma unroll
        for (int mi = 0; mi < 4; mi++) {
            int r = wm * 64 + mi * 16 + g;
            part[wn * 128 + r] = rmax[mi][0];
            part[wn * 128 + r + 8] = rmax[mi][1];
        }
    }
    __syncthreads();
    if (tid < 128) {
        float v = fmaxf(fmaxf(part[tid], part[128 + tid]),
                        fmaxf(part[256 + tid], part[384 + tid]));
        g_md2[(size_t)half * (128 * PP) + (size_t)pair * PP + rowblk * BM + tid] = v;
    }
}

// ---------------------------------------------------------------------------
// Kernel 3 (fused): per n1: combine halves, sp, spbar, per-pair max over p,
// scores -> out[0..7]. One block per n1, 1024 threads (one per p).
// ---------------------------------------------------------------------------
__global__ __launch_bounds__(1024) void spfused_kernel(const float* __restrict__ mask,
                                                       float* __restrict__ out) {
    const int n1 = blockIdx.x;
    const int p  = threadIdx.x;
    const int lane = p & 31;
    const int warp = p >> 5;
    __shared__ float wmax[32][16];
    __shared__ float score[16];

    float mk = mask[n1 * PP + p];
    float sum = 0.f;
    float sps[16];
#pragma unroll
    for (int l = 0; l < LL; l++)
#pragma unroll
        for (int n2 = 0; n2 < NN2; n2++) {
            int w = l * NN2 + n2;
            int pr = (l * NN1 + n1) * NN2 + n2;
            float s = fmaxf(g_md2[pr * PP + p], g_md2[128 * PP + pr * PP + p]);
            float d2 = fmaxf(2.0f - 2.0f * s, 1e-12f);
            float sp = sqrtf(d2) * 0.5f * mk;
            sum += sp;
            sps[w] = sp;
        }
    g_spbar[n1 * PP + p] = sum * (1.0f / 16.0f);

#pragma unroll
    for (int o = 16; o > 0; o >>= 1)
#pragma unroll
        for (int w = 0; w < 16; w++)
            sps[w] = fmaxf(sps[w], __shfl_xor_sync(0xffffffffu, sps[w], o));
    if (lane == 0)
#pragma unroll
        for (int w = 0; w < 16; w++) wmax[warp][w] = sps[w];
    __syncthreads();

    if (warp < 16) {
        float m = wmax[lane][warp];
#pragma unroll
        for (int o = 16; o > 0; o >>= 1)
            m = fmaxf(m, __shfl_xor_sync(0xffffffffu, m, o));
        if (lane == 0) score[warp] = m;
    }
    __syncthreads();
    if (p == 0) {
        float s = 0.f;
#pragma unroll
        for (int w = 0; w < 16; w++) s += score[w];
        out[n1] = s * (1.0f / 16.0f);
    }
}

// ---------------------------------------------------------------------------
// Kernel 4: bilinear resize 32x32 -> 512x512 (half-pixel centers, edge clamp)
// ---------------------------------------------------------------------------
__global__ __launch_bounds__(256) void resize_kernel(float* __restrict__ out) {
    int idx = blockIdx.x * 256 + threadIdx.x;
    if (idx >= NN1 * IMG * IMG) return;
    int n1  = idx >> 18;
    int rem = idx & (IMG * IMG - 1);
    int y = rem >> 9;
    int x = rem & (IMG - 1);

    float sy = (y + 0.5f) * (1.0f / 16.0f) - 0.5f;
    float sx = (x + 0.5f) * (1.0f / 16.0f) - 0.5f;
    int y0 = (int)floorf(sy);
    int x0 = (int)floorf(sx);
    float wy = sy - (float)y0;
    float wx = sx - (float)x0;
    int y0c = min(max(y0, 0), PH - 1);
    int y1c = min(max(y0 + 1, 0), PH - 1);
    int x0c = min(max(x0, 0), PW - 1);
    int x1c = min(max(x0 + 1, 0), PW - 1);

    const float* sb = g_spbar + n1 * PP;
    float v00 = sb[y0c * PW + x0c];
    float v01 = sb[y0c * PW + x1c];
    float v10 = sb[y1c * PW + x0c];
    float v11 = sb[y1c * PW + x1c];
    float v = (1.f - wy) * ((1.f - wx) * v00 + wx * v01)
            +        wy  * ((1.f - wx) * v10 + wx * v11);
    out[8 + idx] = v;
}

// ---------------------------------------------------------------------------
extern "C" void kernel_launch(void* const* d_in, const int* in_sizes, int n_in,
                              void* d_out, int out_size) {
    const float* feats  = (const float*)d_in[0];
    const float* nfeats = (const float*)d_in[1];
    const float* mask   = (const float*)d_in[2];
    float* out = (float*)d_out;

    const int rows = LL * NN1 * PP;  // 16384 rows per tensor

    dim3 ngrid(rows / 8, 2);
    normalize_kernel<<<ngrid, 256>>>(feats, nfeats, rows);

    cudaFuncSetAttribute(distmax_bf16_v9,
                         cudaFuncAttributeMaxDynamicSharedMemorySize, SMEM_BYTES);
    dim3 grid(16, LL * NN1 * NN2);  // (rowblk x colhalf, 128 pairs) = 2048 CTAs
    distmax_bf16_v9<<<grid, 256, SMEM_BYTES>>>();

    spfused_kernel<<<NN1, 1024>>>(mask, out);
    resize_kernel<<<(NN1 * IMG * IMG + 255) / 256, 256>>>(out);
}

// round 15
// speedup vs baseline: 2.0433x; 1.0343x over previous
#include <cuda_runtime.h>
#include <cuda_bf16.h>
#include <math.h>
#include <stdint.h>

#define LL 2
#define NN1 8
#define NN2 8
#define PP 1024
#define DD 768
#define PH 32
#define PW 32
#define IMG 512

// Blocked-swizzled bf16 storage: per matrix (1024x768): 8 rowblocks x 12
// kblocks of contiguous 16KB tiles; tile interior = 128 rows x 8 chunks of
// 16B with chunk' = chunk ^ (row & 7). Matrix stride = 96 tiles = 1.5 MB.
#define TILE_B 16384
#define MAT_B (96 * TILE_B)   // 1572864 bytes

__device__ __nv_bfloat16 g_fa[LL * NN1 * PP * DD];  // blocked-swizzled
__device__ __nv_bfloat16 g_fb[LL * NN2 * PP * DD];  // blocked-swizzled
__device__ float g_md2[2 * LL * NN1 * NN2 * PP];    // per-column-half row max
__device__ float g_spbar[NN1 * PP];

// ---------------------------------------------------------------------------
// Kernel 1: L2-normalize rows of [rows, 768] -> bf16 in blocked-swizzled
// layout. One warp per row; lane handles chunks c = lane, lane+32, lane+64.
// ---------------------------------------------------------------------------
__global__ __launch_bounds__(256) void normalize_kernel(const float* __restrict__ inA,
                                                        const float* __restrict__ inB,
                                                        int nrows) {
    int row  = blockIdx.x * 8 + (threadIdx.x >> 5);
    int lane = threadIdx.x & 31;
    if (row >= nrows) return;
    const float* in = blockIdx.y ? inB : inA;
    char* outb = (char*)(blockIdx.y ? g_fb : g_fa);
    const float4* src = (const float4*)(in + (size_t)row * DD);

    float4 v[6];
    float ss = 0.f;
#pragma unroll
    for (int i = 0; i < 3; i++) {
        v[2 * i + 0] = src[2 * lane + 64 * i];
        v[2 * i + 1] = src[2 * lane + 64 * i + 1];
        ss += v[2*i].x * v[2*i].x + v[2*i].y * v[2*i].y
            + v[2*i].z * v[2*i].z + v[2*i].w * v[2*i].w;
        ss += v[2*i+1].x * v[2*i+1].x + v[2*i+1].y * v[2*i+1].y
            + v[2*i+1].z * v[2*i+1].z + v[2*i+1].w * v[2*i+1].w;
    }
#pragma unroll
    for (int o = 16; o > 0; o >>= 1) ss += __shfl_xor_sync(0xffffffffu, ss, o);
    float inv = 1.0f / sqrtf(ss);

    const int rm = row & (PP - 1);       // row within matrix
    const size_t matoff = (size_t)(row >> 10) * MAT_B;
    const int r7 = rm & 127;
    const uint32_t inner = (uint32_t)(r7 * 128);

#pragma unroll
    for (int i = 0; i < 3; i++) {
        int c = lane + 32 * i;
        __nv_bfloat162 h0 = __floats2bfloat162_rn(v[2*i].x * inv,   v[2*i].y * inv);
        __nv_bfloat162 h1 = __floats2bfloat162_rn(v[2*i].z * inv,   v[2*i].w * inv);
        __nv_bfloat162 h2 = __floats2bfloat162_rn(v[2*i+1].x * inv, v[2*i+1].y * inv);
        __nv_bfloat162 h3 = __floats2bfloat162_rn(v[2*i+1].z * inv, v[2*i+1].w * inv);
        uint4 u;
        u.x = *(uint32_t*)&h0; u.y = *(uint32_t*)&h1;
        u.z = *(uint32_t*)&h2; u.w = *(uint32_t*)&h3;
        size_t addr = matoff
                    + ((size_t)((rm >> 7) * 12 + (c >> 3)) << 14)
                    + inner
                    + (uint32_t)((((c & 7) ^ (r7 & 7)) & 7) << 4);
        *(uint4*)(outb + addr) = u;
    }
}

// ---------------------------------------------------------------------------
// Kernel 2: fused bf16 mma.sync GEMM + row-max (v10 = v9 + mbarrier
// producer/consumer slot tracking; NO per-stage __syncthreads).
// Grid (16,128): blockIdx.x = rowblock(8) x colhalf(2). Each CTA: 128-row
// strip of A x 4 column tiles of 128 = flat 48-stage pipeline. Per stage:
// thread 0 issues 2 x 16KB cp.async.bulk into a 3-slot ring; full[j]
// (expect_tx) signals data, empty[j] (8 warp-arrives) signals consumption.
// 256 thr = 8 warps (2m x 4n), warp tile 64x32, mma.m16n8k16.bf16, 2 CTAs/SM.
// ---------------------------------------------------------------------------
#define BM 128
#define BN 128
#define ABUF 16384            // A tile in slot
#define SLOT (2 * ABUF)       // A+B per ring slot = 32768 B
#define OFF_PART (3 * SLOT)   // 98304
#define SMEM_BYTES (OFF_PART + 4 * 128 * 4)  // 100352
#define NSTG 48               // 4 column tiles x 12 K-stages

__device__ __forceinline__ void ldsm4(uint32_t* r, uint32_t addr) {
    asm volatile("ldmatrix.sync.aligned.m8n8.x4.shared.b16 {%0,%1,%2,%3}, [%4];"
                 : "=r"(r[0]), "=r"(r[1]), "=r"(r[2]), "=r"(r[3]) : "r"(addr));
}

__device__ __forceinline__ void mbar_wait(uint32_t addr, int parity) {
    asm volatile(
        "{\n\t"
        ".reg .pred P1;\n\t"
        "WL_%=:\n\t"
        "mbarrier.try_wait.parity.acquire.cta.shared::cta.b64 P1, [%0], %1, 0x989680;\n\t"
        "@P1 bra.uni WD_%=;\n\t"
        "bra.uni WL_%=;\n\t"
        "WD_%=:\n\t"
        "}"
        :: "r"(addr), "r"(parity) : "memory");
}

__global__ __launch_bounds__(256, 2) void distmax_bf16_v10() {
    extern __shared__ char dsm[];
    __shared__ __align__(8) uint64_t full_s[3];
    __shared__ __align__(8) uint64_t empty_s[3];
    uint32_t sm = (uint32_t)__cvta_generic_to_shared(dsm);
    uint32_t fb = (uint32_t)__cvta_generic_to_shared(full_s);
    uint32_t eb = (uint32_t)__cvta_generic_to_shared(empty_s);
    float* part = (float*)(dsm + OFF_PART);

    const int pair = blockIdx.y;          // ((l*8 + n1)*8 + n2)
    const int l  = pair >> 6;
    const int n1 = (pair >> 3) & 7;
    const int n2 = pair & 7;
    const int rowblk = blockIdx.x & 7;
    const int half   = blockIdx.x >> 3;   // column tiles [half*4, half*4+4)
    const char* Abase = (const char*)g_fa + (size_t)(l * NN1 + n1) * MAT_B;
    const char* Bbase = (const char*)g_fb + (size_t)(l * NN2 + n2) * MAT_B;

    const int tid  = threadIdx.x;
    const int lane = tid & 31;
    const int warp = tid >> 5;
    const int wm = warp >> 2;        // 0..1
    const int wn = warp & 3;         // 0..3
    const int g  = lane >> 2;        // 0..7
    const int t4 = lane & 3;         // 0..3
    const int sub = lane >> 3;       // 0..3 (ldmatrix sub-matrix)
    const int lr8 = lane & 7;

    if (tid == 0) {
#pragma unroll
        for (int j = 0; j < 3; j++) {
            asm volatile("mbarrier.init.shared.b64 [%0], %1;"
                         :: "r"(fb + 8 * j), "r"(1) : "memory");
            asm volatile("mbarrier.init.shared.b64 [%0], %1;"
                         :: "r"(eb + 8 * j), "r"(8) : "memory");
        }
    }
    __syncthreads();

    // ldmatrix addressing (proven fragment map + swizzle):
    const uint32_t aRow = (uint32_t)((wm * 64 + (sub & 1) * 8 + lr8) * 128);
    const uint32_t bRow = (uint32_t)((wn * 32 + (sub >> 1) * 8 + lr8) * 128);
    uint32_t aCk[4], bCk[4];
#pragma unroll
    for (int k16 = 0; k16 < 4; k16++) {
        aCk[k16] = (uint32_t)(((((sub >> 1) + 2 * k16) ^ lr8) & 7) * 16);
        bCk[k16] = (uint32_t)(((((sub & 1) + 2 * k16) ^ lr8) & 7) * 16);
    }

    float rmax[4][2];
#pragma unroll
    for (int i = 0; i < 4; i++) { rmax[i][0] = -2.f; rmax[i][1] = -2.f; }

    // issue(t): thread0 bulk-copies stage t's A+B tiles into slot t%3.
    // For t>=3, first wait consumption #(t/3 - 1) of that slot.
    int ct_n = half * 4, k_n = 0;   // (ct,k) of next stage to issue
    auto issue = [&](int t) {
        if (tid == 0) {
            int j = t % 3;
            int k = t / 3;
            if (k >= 1) mbar_wait(eb + (uint32_t)(j * 8), (k - 1) & 1);
            uint32_t bar = fb + (uint32_t)(j * 8);
            uint32_t dst = sm + (uint32_t)(j * SLOT);
            const char* asrc = Abase + ((size_t)(rowblk * 12 + k_n) << 14);
            const char* bsrc = Bbase + ((size_t)(ct_n * 12 + k_n) << 14);
            asm volatile("fence.proxy.async.shared::cta;" ::: "memory");
            asm volatile("mbarrier.arrive.expect_tx.shared.b64 _, [%0], %1;"
                         :: "r"(bar), "r"(2 * ABUF) : "memory");
            asm volatile(
                "cp.async.bulk.shared::cluster.global.mbarrier::complete_tx::bytes "
                "[%0], [%1], %2, [%3];"
                :: "r"(dst), "l"(asrc), "r"(ABUF), "r"(bar) : "memory");
            asm volatile(
                "cp.async.bulk.shared::cluster.global.mbarrier::complete_tx::bytes "
                "[%0], [%1], %2, [%3];"
                :: "r"(dst + ABUF), "l"(bsrc), "r"(ABUF), "r"(bar) : "memory");
        }
        if (++k_n == 12) { k_n = 0; ct_n++; }
    };

    issue(0);
    issue(1);

    float acc[4][4][4];
    int kc = 0;   // kstep within current column tile
    int cb = 0;   // ring slot of current compute stage

    for (int s = 0; s < NSTG; s++) {
        if (s + 2 < NSTG) issue(s + 2);
        // Acquire-wait: stage-s data visible to this thread.
        mbar_wait(fb + (uint32_t)(cb * 8), (s / 3) & 1);

        if (kc == 0) {
#pragma unroll
            for (int mi = 0; mi < 4; mi++)
#pragma unroll
                for (int ni = 0; ni < 4; ni++)
#pragma unroll
                    for (int r = 0; r < 4; r++) acc[mi][ni][r] = 0.f;
        }

        const uint32_t aBuf = sm + (uint32_t)(cb * SLOT);
        const uint32_t bBuf = aBuf + ABUF;

#pragma unroll
        for (int k16 = 0; k16 < 4; k16++) {
            uint32_t a[4][4], b[2][4];
#pragma unroll
            for (int mi = 0; mi < 4; mi++)
                ldsm4(a[mi], aBuf + aRow + (uint32_t)(mi * 2048) + aCk[k16]);
#pragma unroll
            for (int np = 0; np < 2; np++)
                ldsm4(b[np], bBuf + bRow + (uint32_t)(np * 2048) + bCk[k16]);
#pragma unroll
            for (int mi = 0; mi < 4; mi++)
#pragma unroll
                for (int ni = 0; ni < 4; ni++) {
                    asm volatile(
                        "mma.sync.aligned.m16n8k16.row.col.f32.bf16.bf16.f32 "
                        "{%0,%1,%2,%3},{%4,%5,%6,%7},{%8,%9},{%0,%1,%2,%3};\n"
                        : "+f"(acc[mi][ni][0]), "+f"(acc[mi][ni][1]),
                          "+f"(acc[mi][ni][2]), "+f"(acc[mi][ni][3])
                        : "r"(a[mi][0]), "r"(a[mi][1]), "r"(a[mi][2]), "r"(a[mi][3]),
                          "r"(b[ni >> 1][(ni & 1) * 2]), "r"(b[ni >> 1][(ni & 1) * 2 + 1]));
                }
        }

        // This warp is done reading slot cb for stage s (ldmatrix is
        // warp-synchronous, so all lanes' reads retired). Release-arrive.
        if (lane == 0)
            asm volatile("mbarrier.arrive.shared.b64 _, [%0];"
                         :: "r"(eb + (uint32_t)(cb * 8)) : "memory");

        if (kc == 11) {
            // column tile finished: fold into running row max
#pragma unroll
            for (int mi = 0; mi < 4; mi++) {
                float m0 = -2.f, m1 = -2.f;
#pragma unroll
                for (int ni = 0; ni < 4; ni++) {
                    m0 = fmaxf(m0, fmaxf(acc[mi][ni][0], acc[mi][ni][1]));
                    m1 = fmaxf(m1, fmaxf(acc[mi][ni][2], acc[mi][ni][3]));
                }
                rmax[mi][0] = fmaxf(rmax[mi][0], m0);
                rmax[mi][1] = fmaxf(rmax[mi][1], m1);
            }
            kc = 0;
        } else {
            kc++;
        }
        if (++cb == 3) cb = 0;
    }

    // reduce across the 4 lanes sharing g (t4 = lane&3)
#pragma unroll
    for (int o = 1; o <= 2; o <<= 1) {
#pragma unroll
        for (int mi = 0; mi < 4; mi++) {
            rmax[mi][0] = fmaxf(rmax[mi][0], __shfl_xor_sync(0xffffffffu, rmax[mi][0], o));
            rmax[mi][1] = fmaxf(rmax[mi][1], __shfl_xor_sync(0xffffffffu, rmax[mi][1], o));
        }
    }
    if (t4 == 0) {
#pragma unroll
        for (int mi = 0; mi < 4; mi++) {
            int r = wm * 64 + mi * 16 + g;
            part[wn * 128 + r] = rmax[mi][0];
            part[wn * 128 + r + 8] = rmax[mi][1];
        }
    }
    __syncthreads();
    if (tid < 128) {
        float v = fmaxf(fmaxf(part[tid], part[128 + tid]),
                        fmaxf(part[256 + tid], part[384 + tid]));
        g_md2[(size_t)half * (128 * PP) + (size_t)pair * PP + rowblk * BM + tid] = v;
    }
}

// ---------------------------------------------------------------------------
// Kernel 3 (fused): per n1: combine halves, sp, spbar, per-pair max over p,
// scores -> out[0..7]. One block per n1, 1024 threads (one per p).
// ---------------------------------------------------------------------------
__global__ __launch_bounds__(1024) void spfused_kernel(const float* __restrict__ mask,
                                                       float* __restrict__ out) {
    const int n1 = blockIdx.x;
    const int p  = threadIdx.x;
    const int lane = p & 31;
    const int warp = p >> 5;
    __shared__ float wmax[32][16];
    __shared__ float score[16];

    float mk = mask[n1 * PP + p];
    float sum = 0.f;
    float sps[16];
#pragma unroll
    for (int l = 0; l < LL; l++)
#pragma unroll
        for (int n2 = 0; n2 < NN2; n2++) {
            int w = l * NN2 + n2;
            int pr = (l * NN1 + n1) * NN2 + n2;
            float s = fmaxf(g_md2[pr * PP + p], g_md2[128 * PP + pr * PP + p]);
            float d2 = fmaxf(2.0f - 2.0f * s, 1e-12f);
            float sp = sqrtf(d2) * 0.5f * mk;
            sum += sp;
            sps[w] = sp;
        }
    g_spbar[n1 * PP + p] = sum * (1.0f / 16.0f);

#pragma unroll
    for (int o = 16; o > 0; o >>= 1)
#pragma unroll
        for (int w = 0; w < 16; w++)
            sps[w] = fmaxf(sps[w], __shfl_xor_sync(0xffffffffu, sps[w], o));
    if (lane == 0)
#pragma unroll
        for (int w = 0; w < 16; w++) wmax[warp][w] = sps[w];
    __syncthreads();

    if (warp < 16) {
        float m = wmax[lane][warp];
#pragma unroll
        for (int o = 16; o > 0; o >>= 1)
            m = fmaxf(m, __shfl_xor_sync(0xffffffffu, m, o));
        if (lane == 0) score[warp] = m;
    }
    __syncthreads();
    if (p == 0) {
        float s = 0.f;
#pragma unroll
        for (int w = 0; w < 16; w++) s += score[w];
        out[n1] = s * (1.0f / 16.0f);
    }
}

// ---------------------------------------------------------------------------
// Kernel 4: bilinear resize 32x32 -> 512x512 (half-pixel centers, edge clamp)
// ---------------------------------------------------------------------------
__global__ __launch_bounds__(256) void resize_kernel(float* __restrict__ out) {
    int idx = blockIdx.x * 256 + threadIdx.x;
    if (idx >= NN1 * IMG * IMG) return;
    int n1  = idx >> 18;
    int rem = idx & (IMG * IMG - 1);
    int y = rem >> 9;
    int x = rem & (IMG - 1);

    float sy = (y + 0.5f) * (1.0f / 16.0f) - 0.5f;
    float sx = (x + 0.5f) * (1.0f / 16.0f) - 0.5f;
    int y0 = (int)floorf(sy);
    int x0 = (int)floorf(sx);
    float wy = sy - (float)y0;
    float wx = sx - (float)x0;
    int y0c = min(max(y0, 0), PH - 1);
    int y1c = min(max(y0 + 1, 0), PH - 1);
    int x0c = min(max(x0, 0), PW - 1);
    int x1c = min(max(x0 + 1, 0), PW - 1);

    const float* sb = g_spbar + n1 * PP;
    float v00 = sb[y0c * PW + x0c];
    float v01 = sb[y0c * PW + x1c];
    float v10 = sb[y1c * PW + x0c];
    float v11 = sb[y1c * PW + x1c];
    float v = (1.f - wy) * ((1.f - wx) * v00 + wx * v01)
            +        wy  * ((1.f - wx) * v10 + wx * v11);
    out[8 + idx] = v;
}

// ---------------------------------------------------------------------------
extern "C" void kernel_launch(void* const* d_in, const int* in_sizes, int n_in,
                              void* d_out, int out_size) {
    const float* feats  = (const float*)d_in[0];
    const float* nfeats = (const float*)d_in[1];
    const float* mask   = (const float*)d_in[2];
    float* out = (float*)d_out;

    const int rows = LL * NN1 * PP;  // 16384 rows per tensor

    dim3 ngrid(rows / 8, 2);
    normalize_kernel<<<ngrid, 256>>>(feats, nfeats, rows);

    cudaFuncSetAttribute(distmax_bf16_v10,
                         cudaFuncAttributeMaxDynamicSharedMemorySize, SMEM_BYTES);
    dim3 grid(16, LL * NN1 * NN2);  // (rowblk x colhalf, 128 pairs) = 2048 CTAs
    distmax_bf16_v10<<<grid, 256, SMEM_BYTES>>>();

    spfused_kernel<<<NN1, 1024>>>(mask, out);
    resize_kernel<<<(NN1 * IMG * IMG + 255) / 256, 256>>>(out);
}